// round 3
// baseline (speedup 1.0000x reference)
#include <cuda_runtime.h>
#include <math.h>

// Problem constants
#define BATCH   4
#define T_SEQ   2048
#define CDIM    1024
#define NHEAD   16
#define HD      64               // head dim
#define MROWS   (BATCH * T_SEQ)  // 8192

// Scratch (allocation-free rule: __device__ globals)
__device__ float g_qkv[(size_t)MROWS * 3 * CDIM]; // 96 MB
__device__ float g_y  [(size_t)MROWS * CDIM];     // 32 MB

// ---------------------------------------------------------------------------
// SGEMM: C[M,N] = A[M,K] @ B[K,N] + bias[N]   (A,B,C row-major, fp32)
// 128x128 block tile, BK=16, 256 threads, 8x8 per-thread register tile.
// M,N multiples of 128; K multiple of 16 (true for all our shapes).
// ---------------------------------------------------------------------------
__global__ __launch_bounds__(256)
void sgemm_bias(const float* __restrict__ A, const float* __restrict__ B,
                const float* __restrict__ bias, float* __restrict__ C,
                int M, int N, int K)
{
    const int BM = 128, BN = 128, BK = 16;
    __shared__ float As[16][128 + 4];   // transposed: As[k][m]
    __shared__ float Bs[16][128];       // Bs[k][n]

    int tid = threadIdx.x;
    int tx = tid & 15;       // n-dir 0..15
    int ty = tid >> 4;       // m-dir 0..15
    int bm = blockIdx.y * BM;
    int bn = blockIdx.x * BN;

    const float* Ab = A + (size_t)bm * K;
    const float* Bb = B + bn;

    float acc[8][8];
    #pragma unroll
    for (int i = 0; i < 8; ++i)
        #pragma unroll
        for (int j = 0; j < 8; ++j) acc[i][j] = 0.f;

    for (int k0 = 0; k0 < K; k0 += BK) {
        // A tile 128x16 -> As[k][m] (transposed store)
        {
            int row   = tid >> 2;   // 0..63
            int chunk = tid & 3;    // 0..3 (float4 along K)
            #pragma unroll
            for (int r = 0; r < 2; ++r) {
                int rr = row + r * 64;
                float4 va = *(const float4*)(Ab + (size_t)rr * K + k0 + chunk * 4);
                As[chunk*4+0][rr] = va.x;
                As[chunk*4+1][rr] = va.y;
                As[chunk*4+2][rr] = va.z;
                As[chunk*4+3][rr] = va.w;
            }
        }
        // B tile 16x128 -> Bs[k][n]
        {
            int kr = tid >> 5;   // 0..7
            int c4 = tid & 31;   // 0..31
            #pragma unroll
            for (int r = 0; r < 2; ++r) {
                int kk = kr + r * 8;
                *(float4*)&Bs[kk][c4*4] =
                    *(const float4*)(Bb + (size_t)(k0 + kk) * N + c4 * 4);
            }
        }
        __syncthreads();

        #pragma unroll
        for (int k = 0; k < BK; ++k) {
            float4 a0 = *(const float4*)&As[k][ty*8];
            float4 a1 = *(const float4*)&As[k][ty*8 + 4];
            float4 b0 = *(const float4*)&Bs[k][tx*8];
            float4 b1 = *(const float4*)&Bs[k][tx*8 + 4];
            float af[8] = {a0.x,a0.y,a0.z,a0.w,a1.x,a1.y,a1.z,a1.w};
            float bf[8] = {b0.x,b0.y,b0.z,b0.w,b1.x,b1.y,b1.z,b1.w};
            #pragma unroll
            for (int i = 0; i < 8; ++i)
                #pragma unroll
                for (int j = 0; j < 8; ++j)
                    acc[i][j] += af[i] * bf[j];
        }
        __syncthreads();
    }

    // Epilogue: bias + store (vectorized)
    #pragma unroll
    for (int i = 0; i < 8; ++i) {
        int row = bm + ty*8 + i;
        float* Cr = C + (size_t)row * N + bn + tx*8;
        const float* br = bias + bn + tx*8;
        #pragma unroll
        for (int j = 0; j < 8; j += 4) {
            float4 v;
            v.x = acc[i][j+0] + br[j+0];
            v.y = acc[i][j+1] + br[j+1];
            v.z = acc[i][j+2] + br[j+2];
            v.w = acc[i][j+3] + br[j+3];
            *(float4*)(Cr + j) = v;
        }
    }
}

// ---------------------------------------------------------------------------
// Causal flash attention, fp32, online softmax (log2 domain).
// One block = one (b, h, 64-row q-block). 128 threads (ty 0..15 x tx 0..7):
// thread owns S/O subtile rows [ty*4, ty*4+4) x cols [tx*8, tx*8+8).
// q/k/v are slices of the interleaved qkv buffer (row stride 3*CDIM).
// ---------------------------------------------------------------------------
#define BQ   64
#define BKV  64
#define PADX 4   // padding for float4-accessed tiles (stride 68 floats)
#define PADP 1   // padding for scalar-accessed P tile (stride 65 floats)

__global__ __launch_bounds__(128)
void flash_attn(const float* __restrict__ qkv, float* __restrict__ y)
{
    // Heaviest q-blocks (most k-tiles) launched first
    int qb = gridDim.x - 1 - blockIdx.x;
    int h  = blockIdx.y;
    int b  = blockIdx.z;
    int q0 = qb * BQ;

    int tid = threadIdx.x;
    int tx  = tid & 7;
    int ty  = tid >> 3;

    extern __shared__ float sm[];
    float (*Qt)[BQ  + PADX] = (float(*)[BQ  + PADX]) sm;                          // [HD][..]  Q^T
    float (*Kt)[BKV + PADX] = (float(*)[BKV + PADX])(sm + HD * (BQ + PADX));      // [HD][..]  K^T
    float (*Vs)[HD  + PADX] = (float(*)[HD  + PADX])(sm + HD * (BQ + PADX)
                                                        + HD * (BKV + PADX));     // [BKV][..] V
    float (*Ps)[BKV + PADP] = (float(*)[BKV + PADP])(sm + HD * (BQ + PADX)
                                                        + HD * (BKV + PADX)
                                                        + BKV * (HD + PADX));     // [BQ][..]  P

    const size_t rstride = (size_t)3 * CDIM;
    const float* qbase = qkv + (size_t)b * T_SEQ * rstride + (size_t)h * HD;
    const float* kbase = qbase + CDIM;
    const float* vbase = qbase + 2 * CDIM;

    // Load Q tile transposed: Qt[d][r]
    for (int it = tid; it < BQ * (HD / 4); it += 128) {
        int r  = it >> 4;   // 0..63
        int dc = it & 15;   // 0..15
        float4 v = *(const float4*)(qbase + (size_t)(q0 + r) * rstride + dc * 4);
        Qt[dc*4+0][r] = v.x; Qt[dc*4+1][r] = v.y;
        Qt[dc*4+2][r] = v.z; Qt[dc*4+3][r] = v.w;
    }

    float o[4][8];
    float m_i[4], l_i[4];
    #pragma unroll
    for (int i = 0; i < 4; ++i) {
        m_i[i] = -1e30f; l_i[i] = 0.f;
        #pragma unroll
        for (int j = 0; j < 8; ++j) o[i][j] = 0.f;
    }

    const float SC = 0.125f * 1.4426950408889634f;  // (1/sqrt(hd)) * log2(e)

    int nkt = qb + 1;
    for (int kt = 0; kt < nkt; ++kt) {
        int k0 = kt * BKV;

        __syncthreads();  // previous-iteration smem reads done (also covers Q load)
        // Load K^T and V tiles
        for (int it = tid; it < BKV * (HD / 4); it += 128) {
            int r  = it >> 4;
            int dc = it & 15;
            float4 kv = *(const float4*)(kbase + (size_t)(k0 + r) * rstride + dc * 4);
            Kt[dc*4+0][r] = kv.x; Kt[dc*4+1][r] = kv.y;
            Kt[dc*4+2][r] = kv.z; Kt[dc*4+3][r] = kv.w;
            float4 vv = *(const float4*)(vbase + (size_t)(k0 + r) * rstride + dc * 4);
            *(float4*)&Vs[r][dc*4] = vv;
        }
        __syncthreads();

        // S = Q @ K^T
        float s[4][8];
        #pragma unroll
        for (int i = 0; i < 4; ++i)
            #pragma unroll
            for (int j = 0; j < 8; ++j) s[i][j] = 0.f;

        #pragma unroll 16
        for (int d = 0; d < HD; ++d) {
            float4 qv  = *(const float4*)&Qt[d][ty*4];
            float4 k0v = *(const float4*)&Kt[d][tx*8];
            float4 k1v = *(const float4*)&Kt[d][tx*8 + 4];
            float qa[4] = {qv.x, qv.y, qv.z, qv.w};
            float ka[8] = {k0v.x,k0v.y,k0v.z,k0v.w,k1v.x,k1v.y,k1v.z,k1v.w};
            #pragma unroll
            for (int i = 0; i < 4; ++i)
                #pragma unroll
                for (int j = 0; j < 8; ++j)
                    s[i][j] += qa[i] * ka[j];
        }

        // Scale (log2 domain) + causal mask
        #pragma unroll
        for (int i = 0; i < 4; ++i) {
            int qi = q0 + ty*4 + i;
            #pragma unroll
            for (int j = 0; j < 8; ++j) {
                int kj = k0 + tx*8 + j;
                s[i][j] = (kj <= qi) ? s[i][j] * SC : -1e30f;
            }
        }

        // Online softmax (per row: 8 lanes share a row => xor-shuffle over 1,2,4)
        #pragma unroll
        for (int i = 0; i < 4; ++i) {
            float mx = s[i][0];
            #pragma unroll
            for (int j = 1; j < 8; ++j) mx = fmaxf(mx, s[i][j]);
            mx = fmaxf(mx, __shfl_xor_sync(0xffffffffu, mx, 1));
            mx = fmaxf(mx, __shfl_xor_sync(0xffffffffu, mx, 2));
            mx = fmaxf(mx, __shfl_xor_sync(0xffffffffu, mx, 4));
            float mnew  = fmaxf(m_i[i], mx);
            float scale = exp2f(m_i[i] - mnew);
            float rs = 0.f;
            #pragma unroll
            for (int j = 0; j < 8; ++j) {
                float p = exp2f(s[i][j] - mnew);
                s[i][j] = p;
                rs += p;
            }
            rs += __shfl_xor_sync(0xffffffffu, rs, 1);
            rs += __shfl_xor_sync(0xffffffffu, rs, 2);
            rs += __shfl_xor_sync(0xffffffffu, rs, 4);
            l_i[i] = l_i[i] * scale + rs;
            m_i[i] = mnew;
            #pragma unroll
            for (int j = 0; j < 8; ++j) o[i][j] *= scale;
            #pragma unroll
            for (int j = 0; j < 8; ++j) Ps[ty*4 + i][tx*8 + j] = s[i][j];
        }
        __syncthreads();

        // O += P @ V
        #pragma unroll 8
        for (int k = 0; k < BKV; ++k) {
            float4 v0 = *(const float4*)&Vs[k][tx*8];
            float4 v1 = *(const float4*)&Vs[k][tx*8 + 4];
            float va[8] = {v0.x,v0.y,v0.z,v0.w,v1.x,v1.y,v1.z,v1.w};
            float pa[4];
            #pragma unroll
            for (int i = 0; i < 4; ++i) pa[i] = Ps[ty*4 + i][k];
            #pragma unroll
            for (int i = 0; i < 4; ++i)
                #pragma unroll
                for (int j = 0; j < 8; ++j)
                    o[i][j] += pa[i] * va[j];
        }
    }

    // Epilogue: normalize and write y[b, q0+row, h*HD + col]
    #pragma unroll
    for (int i = 0; i < 4; ++i) {
        float inv = 1.f / l_i[i];
        int row = q0 + ty*4 + i;
        float* yr = y + ((size_t)b * T_SEQ + row) * CDIM + (size_t)h * HD + tx*8;
        float4 w0, w1;
        w0.x = o[i][0]*inv; w0.y = o[i][1]*inv; w0.z = o[i][2]*inv; w0.w = o[i][3]*inv;
        w1.x = o[i][4]*inv; w1.y = o[i][5]*inv; w1.z = o[i][6]*inv; w1.w = o[i][7]*inv;
        *(float4*)(yr)     = w0;
        *(float4*)(yr + 4) = w1;
    }
}

// ---------------------------------------------------------------------------
// kernel_launch
// inputs (metadata order): x [4,2048,1024] f32, W_attn [1024,3072] f32,
//                          b_attn [3072] f32, W_proj [1024,1024] f32, b_proj [1024] f32
// output: [4,2048,1024] f32
// ---------------------------------------------------------------------------
extern "C" void kernel_launch(void* const* d_in, const int* in_sizes, int n_in,
                              void* d_out, int out_size)
{
    (void)in_sizes; (void)n_in; (void)out_size;
    const float* x      = (const float*)d_in[0];
    const float* W_attn = (const float*)d_in[1];
    const float* b_attn = (const float*)d_in[2];
    const float* W_proj = (const float*)d_in[3];
    const float* b_proj = (const float*)d_in[4];
    float* out = (float*)d_out;

    float* qkv; cudaGetSymbolAddress((void**)&qkv, g_qkv);
    float* yb;  cudaGetSymbolAddress((void**)&yb,  g_y);

    // Flash kernel needs > 48KB dynamic smem
    const int FLASH_SMEM =
        (HD*(BQ+PADX) + HD*(BKV+PADX) + BKV*(HD+PADX) + BQ*(BKV+PADP)) * (int)sizeof(float);
    cudaFuncSetAttribute(flash_attn, cudaFuncAttributeMaxDynamicSharedMemorySize, FLASH_SMEM);

    // 1) qkv = x @ W_attn + b_attn    [8192, 3072]
    {
        dim3 grid(3 * CDIM / 128, MROWS / 128);
        sgemm_bias<<<grid, 256>>>(x, W_attn, b_attn, qkv, MROWS, 3 * CDIM, CDIM);
    }
    // 2) flash attention -> y  [8192, 1024]
    {
        dim3 grid(T_SEQ / BQ, NHEAD, BATCH);
        flash_attn<<<grid, 128, FLASH_SMEM>>>(qkv, yb);
    }
    // 3) out = y @ W_proj + b_proj   [8192, 1024]
    {
        dim3 grid(CDIM / 128, MROWS / 128);
        sgemm_bias<<<grid, 256>>>(yb, W_proj, b_proj, out, MROWS, CDIM, CDIM);
    }
}

// round 4
// speedup vs baseline: 1.4455x; 1.4455x over previous
#include <cuda_runtime.h>
#include <cuda_bf16.h>
#include <math.h>
#include <stdint.h>

// Problem constants
#define BATCH   4
#define T_SEQ   2048
#define CDIM    1024
#define NHEAD   16
#define HD      64
#define MROWS   (BATCH * T_SEQ)  // 8192

// ---------------------------------------------------------------------------
// Scratch (allocation-free rule: __device__ globals)
// ---------------------------------------------------------------------------
__device__ float g_qkv[(size_t)MROWS * 3 * CDIM];         // 96 MB fp32
__device__ float g_y  [(size_t)MROWS * CDIM];             // 32 MB fp32
__device__ __nv_bfloat16 g_xh[(size_t)MROWS * CDIM];      // 16 MB
__device__ __nv_bfloat16 g_xl[(size_t)MROWS * CDIM];
__device__ __nv_bfloat16 g_yh[(size_t)MROWS * CDIM];
__device__ __nv_bfloat16 g_yl[(size_t)MROWS * CDIM];
__device__ __nv_bfloat16 g_wah[(size_t)3 * CDIM * CDIM];  // W_attn^T hi  [3072][1024]
__device__ __nv_bfloat16 g_wal[(size_t)3 * CDIM * CDIM];
__device__ __nv_bfloat16 g_wph[(size_t)CDIM * CDIM];      // W_proj^T hi  [1024][1024]
__device__ __nv_bfloat16 g_wpl[(size_t)CDIM * CDIM];

// ---------------------------------------------------------------------------
// PTX helpers
// ---------------------------------------------------------------------------
__device__ __forceinline__ void cp16(void* dst, const void* src) {
    uint32_t d = (uint32_t)__cvta_generic_to_shared(dst);
    asm volatile("cp.async.cg.shared.global [%0], [%1], 16;\n" :: "r"(d), "l"(src));
}
__device__ __forceinline__ void cp_commit() {
    asm volatile("cp.async.commit_group;\n" ::: "memory");
}
template <int N> __device__ __forceinline__ void cp_wait() {
    asm volatile("cp.async.wait_group %0;\n" :: "n"(N) : "memory");
}
__device__ __forceinline__ void ldm_x4(uint32_t* r, const void* p) {
    uint32_t a = (uint32_t)__cvta_generic_to_shared(p);
    asm volatile("ldmatrix.sync.aligned.m8n8.x4.shared.b16 {%0,%1,%2,%3},[%4];\n"
                 : "=r"(r[0]), "=r"(r[1]), "=r"(r[2]), "=r"(r[3]) : "r"(a));
}
__device__ __forceinline__ void ldm_x2(uint32_t* r, const void* p) {
    uint32_t a = (uint32_t)__cvta_generic_to_shared(p);
    asm volatile("ldmatrix.sync.aligned.m8n8.x2.shared.b16 {%0,%1},[%2];\n"
                 : "=r"(r[0]), "=r"(r[1]) : "r"(a));
}
__device__ __forceinline__ void mma_bf16(float* c, const uint32_t* a, const uint32_t* b) {
    asm volatile(
        "mma.sync.aligned.m16n8k16.row.col.f32.bf16.bf16.f32 "
        "{%0,%1,%2,%3},{%4,%5,%6,%7},{%8,%9},{%0,%1,%2,%3};\n"
        : "+f"(c[0]), "+f"(c[1]), "+f"(c[2]), "+f"(c[3])
        : "r"(a[0]), "r"(a[1]), "r"(a[2]), "r"(a[3]), "r"(b[0]), "r"(b[1]));
}

// ---------------------------------------------------------------------------
// Split conversion: fp32 -> hi bf16 + lo bf16 (same layout). n % 4 == 0.
// ---------------------------------------------------------------------------
__global__ __launch_bounds__(256)
void split_kernel(const float* __restrict__ in, __nv_bfloat16* __restrict__ hi,
                  __nv_bfloat16* __restrict__ lo, int n4)
{
    int i = blockIdx.x * blockDim.x + threadIdx.x;
    if (i >= n4) return;
    float4 v = ((const float4*)in)[i];
    __nv_bfloat16 h[4], l[4];
    float vv[4] = {v.x, v.y, v.z, v.w};
    #pragma unroll
    for (int j = 0; j < 4; ++j) {
        h[j] = __float2bfloat16_rn(vv[j]);
        l[j] = __float2bfloat16_rn(vv[j] - __bfloat162float(h[j]));
    }
    ((uint2*)hi)[i] = *(uint2*)h;
    ((uint2*)lo)[i] = *(uint2*)l;
}

// ---------------------------------------------------------------------------
// Split + transpose: W [K][N] fp32 -> hiT, loT [N][K] bf16. K,N % 32 == 0.
// ---------------------------------------------------------------------------
__global__ __launch_bounds__(256)
void split_transpose_kernel(const float* __restrict__ W,
                            __nv_bfloat16* __restrict__ hiT,
                            __nv_bfloat16* __restrict__ loT, int K, int N)
{
    __shared__ float t[32][33];
    int n0 = blockIdx.x * 32;
    int k0 = blockIdx.y * 32;
    int tx = threadIdx.x, ty = threadIdx.y;   // 32 x 8
    #pragma unroll
    for (int r = 0; r < 32; r += 8)
        t[ty + r][tx] = W[(size_t)(k0 + ty + r) * N + n0 + tx];
    __syncthreads();
    #pragma unroll
    for (int r = 0; r < 32; r += 8) {
        float v = t[tx][ty + r];   // = W[k0+tx][n0+ty+r]
        __nv_bfloat16 h = __float2bfloat16_rn(v);
        __nv_bfloat16 l = __float2bfloat16_rn(v - __bfloat162float(h));
        size_t o = (size_t)(n0 + ty + r) * K + k0 + tx;
        hiT[o] = h;
        loT[o] = l;
    }
}

// ---------------------------------------------------------------------------
// Split-bf16 tensor-core GEMM:
//   C[M][N] = (Ah+Al)[M][K] @ (Bh+Bl)^T  + bias[N]   (3-term: hh + hl + lh)
// A row-major [M][K], B transposed [N][K] — both k-contiguous.
// Tile 256x128x32, 512 threads (16 warps, 4x4), warp tile 64x32.
// ---------------------------------------------------------------------------
#define GBM 256
#define GBN 128
#define GBK 32
#define GROW (GBK + 8)                 // padded row: 40 bf16 = 80B
#define A_TILE (GBM * GROW)            // 10240 bf16
#define B_TILE (GBN * GROW)            // 5120 bf16
#define STAGE_ELEMS (2 * A_TILE + 2 * B_TILE)  // 30720 bf16
#define GEMM_SMEM_BYTES (2 * STAGE_ELEMS * 2)  // 122880 B

__global__ __launch_bounds__(512, 1)
void gemm_split_bf16(const __nv_bfloat16* __restrict__ Ah_g,
                     const __nv_bfloat16* __restrict__ Al_g,
                     const __nv_bfloat16* __restrict__ Bh_g,
                     const __nv_bfloat16* __restrict__ Bl_g,
                     const float* __restrict__ bias, float* __restrict__ C,
                     int M, int N, int K)
{
    extern __shared__ __nv_bfloat16 smem[];
    const int tid  = threadIdx.x;
    const int bm   = blockIdx.y * GBM;
    const int bn   = blockIdx.x * GBN;
    const int warp = tid >> 5, lane = tid & 31;
    const int wm   = (warp & 3) * 64;
    const int wn   = (warp >> 2) * 32;

    float acc[4][4][4];
    #pragma unroll
    for (int i = 0; i < 4; ++i)
        #pragma unroll
        for (int j = 0; j < 4; ++j)
            #pragma unroll
            for (int r = 0; r < 4; ++r) acc[i][j][r] = 0.f;

    // stage loader
    auto load_stage = [&](int s, int k0) {
        __nv_bfloat16* Ah = smem + s * STAGE_ELEMS;
        __nv_bfloat16* Al = Ah + A_TILE;
        __nv_bfloat16* Bh = Al + A_TILE;
        __nv_bfloat16* Bl = Bh + B_TILE;
        #pragma unroll
        for (int c = tid; c < GBM * 4; c += 512) {
            int row = c >> 2, col = (c & 3) * 8;
            size_t g = (size_t)(bm + row) * K + k0 + col;
            cp16(Ah + row * GROW + col, Ah_g + g);
            cp16(Al + row * GROW + col, Al_g + g);
        }
        {
            int c = tid;
            if (c < GBN * 4) {
                int row = c >> 2, col = (c & 3) * 8;
                size_t g = (size_t)(bn + row) * K + k0 + col;
                cp16(Bh + row * GROW + col, Bh_g + g);
                cp16(Bl + row * GROW + col, Bl_g + g);
            }
        }
    };

    const int niter = K / GBK;
    load_stage(0, 0);
    cp_commit();

    for (int it = 0; it < niter; ++it) {
        if (it + 1 < niter) {
            load_stage((it + 1) & 1, (it + 1) * GBK);
            cp_commit();
            cp_wait<1>();
        } else {
            cp_wait<0>();
        }
        __syncthreads();

        const __nv_bfloat16* Ah = smem + (it & 1) * STAGE_ELEMS;
        const __nv_bfloat16* Al = Ah + A_TILE;
        const __nv_bfloat16* Bh = Al + A_TILE;
        const __nv_bfloat16* Bl = Bh + B_TILE;

        #pragma unroll
        for (int kk = 0; kk < GBK; kk += 16) {
            const int arow = wm + (lane & 15);
            const int acol = kk + (lane >> 4) * 8;
            const int brow = wn + (lane & 7);
            const int bcol = kk + ((lane >> 3) & 1) * 8;

            uint32_t afh[4][4], afl[4][4], bfh[4][2], bfl[4][2];
            #pragma unroll
            for (int mt = 0; mt < 4; ++mt)
                ldm_x4(afh[mt], Ah + (arow + mt * 16) * GROW + acol);
            #pragma unroll
            for (int nt = 0; nt < 4; ++nt)
                ldm_x2(bfh[nt], Bh + (brow + nt * 8) * GROW + bcol);

            // hi * hi
            #pragma unroll
            for (int mt = 0; mt < 4; ++mt)
                #pragma unroll
                for (int nt = 0; nt < 4; ++nt)
                    mma_bf16(acc[mt][nt], afh[mt], bfh[nt]);

            // hi * lo
            #pragma unroll
            for (int nt = 0; nt < 4; ++nt)
                ldm_x2(bfl[nt], Bl + (brow + nt * 8) * GROW + bcol);
            #pragma unroll
            for (int mt = 0; mt < 4; ++mt)
                #pragma unroll
                for (int nt = 0; nt < 4; ++nt)
                    mma_bf16(acc[mt][nt], afh[mt], bfl[nt]);

            // lo * hi
            #pragma unroll
            for (int mt = 0; mt < 4; ++mt)
                ldm_x4(afl[mt], Al + (arow + mt * 16) * GROW + acol);
            #pragma unroll
            for (int mt = 0; mt < 4; ++mt)
                #pragma unroll
                for (int nt = 0; nt < 4; ++nt)
                    mma_bf16(acc[mt][nt], afl[mt], bfh[nt]);
        }
        __syncthreads();
    }

    // Epilogue: bias + store
    #pragma unroll
    for (int mt = 0; mt < 4; ++mt) {
        int r0 = bm + wm + mt * 16 + (lane >> 2);
        #pragma unroll
        for (int nt = 0; nt < 4; ++nt) {
            int cc = bn + wn + nt * 8 + (lane & 3) * 2;
            float b0 = bias[cc], b1 = bias[cc + 1];
            float2 v0 = {acc[mt][nt][0] + b0, acc[mt][nt][1] + b1};
            float2 v1 = {acc[mt][nt][2] + b0, acc[mt][nt][3] + b1};
            *(float2*)(C + (size_t)r0 * N + cc)       = v0;
            *(float2*)(C + (size_t)(r0 + 8) * N + cc) = v1;
        }
    }
}

// ---------------------------------------------------------------------------
// Causal flash attention, fp32 (unchanged from passing baseline).
// ---------------------------------------------------------------------------
#define BQ   64
#define BKV  64
#define PADX 4
#define PADP 1

__global__ __launch_bounds__(128)
void flash_attn(const float* __restrict__ qkv, float* __restrict__ y)
{
    int qb = gridDim.x - 1 - blockIdx.x;
    int h  = blockIdx.y;
    int b  = blockIdx.z;
    int q0 = qb * BQ;

    int tid = threadIdx.x;
    int tx  = tid & 7;
    int ty  = tid >> 3;

    extern __shared__ float sm[];
    float (*Qt)[BQ  + PADX] = (float(*)[BQ  + PADX]) sm;
    float (*Kt)[BKV + PADX] = (float(*)[BKV + PADX])(sm + HD * (BQ + PADX));
    float (*Vs)[HD  + PADX] = (float(*)[HD  + PADX])(sm + HD * (BQ + PADX)
                                                        + HD * (BKV + PADX));
    float (*Ps)[BKV + PADP] = (float(*)[BKV + PADP])(sm + HD * (BQ + PADX)
                                                        + HD * (BKV + PADX)
                                                        + BKV * (HD + PADX));

    const size_t rstride = (size_t)3 * CDIM;
    const float* qbase = qkv + (size_t)b * T_SEQ * rstride + (size_t)h * HD;
    const float* kbase = qbase + CDIM;
    const float* vbase = qbase + 2 * CDIM;

    for (int it = tid; it < BQ * (HD / 4); it += 128) {
        int r  = it >> 4;
        int dc = it & 15;
        float4 v = *(const float4*)(qbase + (size_t)(q0 + r) * rstride + dc * 4);
        Qt[dc*4+0][r] = v.x; Qt[dc*4+1][r] = v.y;
        Qt[dc*4+2][r] = v.z; Qt[dc*4+3][r] = v.w;
    }

    float o[4][8];
    float m_i[4], l_i[4];
    #pragma unroll
    for (int i = 0; i < 4; ++i) {
        m_i[i] = -1e30f; l_i[i] = 0.f;
        #pragma unroll
        for (int j = 0; j < 8; ++j) o[i][j] = 0.f;
    }

    const float SC = 0.125f * 1.4426950408889634f;

    int nkt = qb + 1;
    for (int kt = 0; kt < nkt; ++kt) {
        int k0 = kt * BKV;

        __syncthreads();
        for (int it = tid; it < BKV * (HD / 4); it += 128) {
            int r  = it >> 4;
            int dc = it & 15;
            float4 kv = *(const float4*)(kbase + (size_t)(k0 + r) * rstride + dc * 4);
            Kt[dc*4+0][r] = kv.x; Kt[dc*4+1][r] = kv.y;
            Kt[dc*4+2][r] = kv.z; Kt[dc*4+3][r] = kv.w;
            float4 vv = *(const float4*)(vbase + (size_t)(k0 + r) * rstride + dc * 4);
            *(float4*)&Vs[r][dc*4] = vv;
        }
        __syncthreads();

        float s[4][8];
        #pragma unroll
        for (int i = 0; i < 4; ++i)
            #pragma unroll
            for (int j = 0; j < 8; ++j) s[i][j] = 0.f;

        #pragma unroll 16
        for (int d = 0; d < HD; ++d) {
            float4 qv  = *(const float4*)&Qt[d][ty*4];
            float4 k0v = *(const float4*)&Kt[d][tx*8];
            float4 k1v = *(const float4*)&Kt[d][tx*8 + 4];
            float qa[4] = {qv.x, qv.y, qv.z, qv.w};
            float ka[8] = {k0v.x,k0v.y,k0v.z,k0v.w,k1v.x,k1v.y,k1v.z,k1v.w};
            #pragma unroll
            for (int i = 0; i < 4; ++i)
                #pragma unroll
                for (int j = 0; j < 8; ++j)
                    s[i][j] += qa[i] * ka[j];
        }

        #pragma unroll
        for (int i = 0; i < 4; ++i) {
            int qi = q0 + ty*4 + i;
            #pragma unroll
            for (int j = 0; j < 8; ++j) {
                int kj = k0 + tx*8 + j;
                s[i][j] = (kj <= qi) ? s[i][j] * SC : -1e30f;
            }
        }

        #pragma unroll
        for (int i = 0; i < 4; ++i) {
            float mx = s[i][0];
            #pragma unroll
            for (int j = 1; j < 8; ++j) mx = fmaxf(mx, s[i][j]);
            mx = fmaxf(mx, __shfl_xor_sync(0xffffffffu, mx, 1));
            mx = fmaxf(mx, __shfl_xor_sync(0xffffffffu, mx, 2));
            mx = fmaxf(mx, __shfl_xor_sync(0xffffffffu, mx, 4));
            float mnew  = fmaxf(m_i[i], mx);
            float scale = exp2f(m_i[i] - mnew);
            float rs = 0.f;
            #pragma unroll
            for (int j = 0; j < 8; ++j) {
                float p = exp2f(s[i][j] - mnew);
                s[i][j] = p;
                rs += p;
            }
            rs += __shfl_xor_sync(0xffffffffu, rs, 1);
            rs += __shfl_xor_sync(0xffffffffu, rs, 2);
            rs += __shfl_xor_sync(0xffffffffu, rs, 4);
            l_i[i] = l_i[i] * scale + rs;
            m_i[i] = mnew;
            #pragma unroll
            for (int j = 0; j < 8; ++j) o[i][j] *= scale;
            #pragma unroll
            for (int j = 0; j < 8; ++j) Ps[ty*4 + i][tx*8 + j] = s[i][j];
        }
        __syncthreads();

        #pragma unroll 8
        for (int k = 0; k < BKV; ++k) {
            float4 v0 = *(const float4*)&Vs[k][tx*8];
            float4 v1 = *(const float4*)&Vs[k][tx*8 + 4];
            float va[8] = {v0.x,v0.y,v0.z,v0.w,v1.x,v1.y,v1.z,v1.w};
            float pa[4];
            #pragma unroll
            for (int i = 0; i < 4; ++i) pa[i] = Ps[ty*4 + i][k];
            #pragma unroll
            for (int i = 0; i < 4; ++i)
                #pragma unroll
                for (int j = 0; j < 8; ++j)
                    o[i][j] += pa[i] * va[j];
        }
    }

    #pragma unroll
    for (int i = 0; i < 4; ++i) {
        float inv = 1.f / l_i[i];
        int row = q0 + ty*4 + i;
        float* yr = y + ((size_t)b * T_SEQ + row) * CDIM + (size_t)h * HD + tx*8;
        float4 w0, w1;
        w0.x = o[i][0]*inv; w0.y = o[i][1]*inv; w0.z = o[i][2]*inv; w0.w = o[i][3]*inv;
        w1.x = o[i][4]*inv; w1.y = o[i][5]*inv; w1.z = o[i][6]*inv; w1.w = o[i][7]*inv;
        *(float4*)(yr)     = w0;
        *(float4*)(yr + 4) = w1;
    }
}

// ---------------------------------------------------------------------------
// kernel_launch
// ---------------------------------------------------------------------------
extern "C" void kernel_launch(void* const* d_in, const int* in_sizes, int n_in,
                              void* d_out, int out_size)
{
    (void)in_sizes; (void)n_in; (void)out_size;
    const float* x      = (const float*)d_in[0];
    const float* W_attn = (const float*)d_in[1];
    const float* b_attn = (const float*)d_in[2];
    const float* W_proj = (const float*)d_in[3];
    const float* b_proj = (const float*)d_in[4];
    float* out = (float*)d_out;

    float *qkv, *yb;
    __nv_bfloat16 *xh, *xl, *yh, *yl, *wah, *wal, *wph, *wpl;
    cudaGetSymbolAddress((void**)&qkv, g_qkv);
    cudaGetSymbolAddress((void**)&yb,  g_y);
    cudaGetSymbolAddress((void**)&xh,  g_xh);
    cudaGetSymbolAddress((void**)&xl,  g_xl);
    cudaGetSymbolAddress((void**)&yh,  g_yh);
    cudaGetSymbolAddress((void**)&yl,  g_yl);
    cudaGetSymbolAddress((void**)&wah, g_wah);
    cudaGetSymbolAddress((void**)&wal, g_wal);
    cudaGetSymbolAddress((void**)&wph, g_wph);
    cudaGetSymbolAddress((void**)&wpl, g_wpl);

    const int FLASH_SMEM =
        (HD*(BQ+PADX) + HD*(BKV+PADX) + BKV*(HD+PADX) + BQ*(BKV+PADP)) * (int)sizeof(float);
    cudaFuncSetAttribute(flash_attn, cudaFuncAttributeMaxDynamicSharedMemorySize, FLASH_SMEM);
    cudaFuncSetAttribute(gemm_split_bf16, cudaFuncAttributeMaxDynamicSharedMemorySize,
                         GEMM_SMEM_BYTES);

    // 1) split x
    {
        int n4 = MROWS * CDIM / 4;
        split_kernel<<<(n4 + 255) / 256, 256>>>(x, xh, xl, n4);
    }
    // 2) split + transpose weights
    {
        dim3 blk(32, 8);
        split_transpose_kernel<<<dim3(3 * CDIM / 32, CDIM / 32), blk>>>(W_attn, wah, wal, CDIM, 3 * CDIM);
        split_transpose_kernel<<<dim3(CDIM / 32, CDIM / 32), blk>>>(W_proj, wph, wpl, CDIM, CDIM);
    }
    // 3) qkv = x @ W_attn + b_attn  [8192, 3072]
    {
        dim3 grid(3 * CDIM / GBN, MROWS / GBM);
        gemm_split_bf16<<<grid, 512, GEMM_SMEM_BYTES>>>(xh, xl, wah, wal, b_attn, qkv,
                                                        MROWS, 3 * CDIM, CDIM);
    }
    // 4) flash attention -> y [8192, 1024]
    {
        dim3 grid(T_SEQ / BQ, NHEAD, BATCH);
        flash_attn<<<grid, 128, FLASH_SMEM>>>(qkv, yb);
    }
    // 5) split y
    {
        int n4 = MROWS * CDIM / 4;
        split_kernel<<<(n4 + 255) / 256, 256>>>(yb, yh, yl, n4);
    }
    // 6) out = y @ W_proj + b_proj  [8192, 1024]
    {
        dim3 grid(CDIM / GBN, MROWS / GBM);
        gemm_split_bf16<<<grid, 512, GEMM_SMEM_BYTES>>>(yh, yl, wph, wpl, b_proj, out,
                                                        MROWS, CDIM, CDIM);
    }
}

// round 5
// speedup vs baseline: 2.7781x; 1.9219x over previous
#include <cuda_runtime.h>
#include <cuda_bf16.h>
#include <math.h>
#include <stdint.h>

// Problem constants
#define BATCH   4
#define T_SEQ   2048
#define CDIM    1024
#define NHEAD   16
#define HD      64
#define MROWS   (BATCH * T_SEQ)  // 8192

// ---------------------------------------------------------------------------
// Scratch (allocation-free rule: __device__ globals)
// ---------------------------------------------------------------------------
__device__ __nv_bfloat16 g_xh[(size_t)MROWS * CDIM];
__device__ __nv_bfloat16 g_xl[(size_t)MROWS * CDIM];
__device__ __nv_bfloat16 g_qkvh[(size_t)MROWS * 3 * CDIM];   // 48 MB
__device__ __nv_bfloat16 g_qkvl[(size_t)MROWS * 3 * CDIM];
__device__ __nv_bfloat16 g_yh[(size_t)MROWS * CDIM];
__device__ __nv_bfloat16 g_yl[(size_t)MROWS * CDIM];
__device__ __nv_bfloat16 g_wah[(size_t)3 * CDIM * CDIM];     // W_attn^T hi [3072][1024]
__device__ __nv_bfloat16 g_wal[(size_t)3 * CDIM * CDIM];
__device__ __nv_bfloat16 g_wph[(size_t)CDIM * CDIM];
__device__ __nv_bfloat16 g_wpl[(size_t)CDIM * CDIM];

// ---------------------------------------------------------------------------
// PTX helpers
// ---------------------------------------------------------------------------
__device__ __forceinline__ void cp16(void* dst, const void* src) {
    uint32_t d = (uint32_t)__cvta_generic_to_shared(dst);
    asm volatile("cp.async.cg.shared.global [%0], [%1], 16;\n" :: "r"(d), "l"(src));
}
__device__ __forceinline__ void cp_commit() {
    asm volatile("cp.async.commit_group;\n" ::: "memory");
}
template <int N> __device__ __forceinline__ void cp_wait() {
    asm volatile("cp.async.wait_group %0;\n" :: "n"(N) : "memory");
}
__device__ __forceinline__ void ldm_x4(uint32_t* r, const void* p) {
    uint32_t a = (uint32_t)__cvta_generic_to_shared(p);
    asm volatile("ldmatrix.sync.aligned.m8n8.x4.shared.b16 {%0,%1,%2,%3},[%4];\n"
                 : "=r"(r[0]), "=r"(r[1]), "=r"(r[2]), "=r"(r[3]) : "r"(a));
}
__device__ __forceinline__ void ldm_x2(uint32_t* r, const void* p) {
    uint32_t a = (uint32_t)__cvta_generic_to_shared(p);
    asm volatile("ldmatrix.sync.aligned.m8n8.x2.shared.b16 {%0,%1},[%2];\n"
                 : "=r"(r[0]), "=r"(r[1]) : "r"(a));
}
__device__ __forceinline__ void ldm_x2t(uint32_t* r, const void* p) {
    uint32_t a = (uint32_t)__cvta_generic_to_shared(p);
    asm volatile("ldmatrix.sync.aligned.m8n8.x2.trans.shared.b16 {%0,%1},[%2];\n"
                 : "=r"(r[0]), "=r"(r[1]) : "r"(a));
}
__device__ __forceinline__ void mma_bf16(float* c, const uint32_t* a, const uint32_t* b) {
    asm volatile(
        "mma.sync.aligned.m16n8k16.row.col.f32.bf16.bf16.f32 "
        "{%0,%1,%2,%3},{%4,%5,%6,%7},{%8,%9},{%0,%1,%2,%3};\n"
        : "+f"(c[0]), "+f"(c[1]), "+f"(c[2]), "+f"(c[3])
        : "r"(a[0]), "r"(a[1]), "r"(a[2]), "r"(a[3]), "r"(b[0]), "r"(b[1]));
}
// split two floats into packed-bf16 hi and lo pairs
__device__ __forceinline__ void splitpack2(float a, float b, uint32_t& hi, uint32_t& lo) {
    __nv_bfloat16 ha = __float2bfloat16_rn(a);
    __nv_bfloat16 hb = __float2bfloat16_rn(b);
    __nv_bfloat16 la = __float2bfloat16_rn(a - __bfloat162float(ha));
    __nv_bfloat16 lb = __float2bfloat16_rn(b - __bfloat162float(hb));
    hi = (uint32_t)(*(uint16_t*)&ha) | ((uint32_t)(*(uint16_t*)&hb) << 16);
    lo = (uint32_t)(*(uint16_t*)&la) | ((uint32_t)(*(uint16_t*)&lb) << 16);
}

// ---------------------------------------------------------------------------
// Split conversion: fp32 -> hi + lo bf16
// ---------------------------------------------------------------------------
__global__ __launch_bounds__(256)
void split_kernel(const float* __restrict__ in, __nv_bfloat16* __restrict__ hi,
                  __nv_bfloat16* __restrict__ lo, int n4)
{
    int i = blockIdx.x * blockDim.x + threadIdx.x;
    if (i >= n4) return;
    float4 v = ((const float4*)in)[i];
    __nv_bfloat16 h[4], l[4];
    float vv[4] = {v.x, v.y, v.z, v.w};
    #pragma unroll
    for (int j = 0; j < 4; ++j) {
        h[j] = __float2bfloat16_rn(vv[j]);
        l[j] = __float2bfloat16_rn(vv[j] - __bfloat162float(h[j]));
    }
    ((uint2*)hi)[i] = *(uint2*)h;
    ((uint2*)lo)[i] = *(uint2*)l;
}

// ---------------------------------------------------------------------------
// Split + transpose: W [K][N] fp32 -> hiT, loT [N][K] bf16
// ---------------------------------------------------------------------------
__global__ __launch_bounds__(256)
void split_transpose_kernel(const float* __restrict__ W,
                            __nv_bfloat16* __restrict__ hiT,
                            __nv_bfloat16* __restrict__ loT, int K, int N)
{
    __shared__ float t[32][33];
    int n0 = blockIdx.x * 32;
    int k0 = blockIdx.y * 32;
    int tx = threadIdx.x, ty = threadIdx.y;   // 32 x 8
    #pragma unroll
    for (int r = 0; r < 32; r += 8)
        t[ty + r][tx] = W[(size_t)(k0 + ty + r) * N + n0 + tx];
    __syncthreads();
    #pragma unroll
    for (int r = 0; r < 32; r += 8) {
        float v = t[tx][ty + r];
        __nv_bfloat16 h = __float2bfloat16_rn(v);
        __nv_bfloat16 l = __float2bfloat16_rn(v - __bfloat162float(h));
        size_t o = (size_t)(n0 + ty + r) * K + k0 + tx;
        hiT[o] = h;
        loT[o] = l;
    }
}

// ---------------------------------------------------------------------------
// Split-bf16 tensor-core GEMM (3-term). Epilogue: either fp32 C, or bf16 hi/lo.
// ---------------------------------------------------------------------------
#define GBM 256
#define GBN 128
#define GBK 32
#define GROW (GBK + 8)
#define A_TILE (GBM * GROW)
#define B_TILE (GBN * GROW)
#define STAGE_ELEMS (2 * A_TILE + 2 * B_TILE)
#define GEMM_SMEM_BYTES (2 * STAGE_ELEMS * 2)

__global__ __launch_bounds__(512, 1)
void gemm_split_bf16(const __nv_bfloat16* __restrict__ Ah_g,
                     const __nv_bfloat16* __restrict__ Al_g,
                     const __nv_bfloat16* __restrict__ Bh_g,
                     const __nv_bfloat16* __restrict__ Bl_g,
                     const float* __restrict__ bias,
                     float* __restrict__ Cf,
                     __nv_bfloat16* __restrict__ Chi,
                     __nv_bfloat16* __restrict__ Clo,
                     int M, int N, int K)
{
    extern __shared__ __nv_bfloat16 smem[];
    const int tid  = threadIdx.x;
    const int bm   = blockIdx.y * GBM;
    const int bn   = blockIdx.x * GBN;
    const int warp = tid >> 5, lane = tid & 31;
    const int wm   = (warp & 3) * 64;
    const int wn   = (warp >> 2) * 32;

    float acc[4][4][4];
    #pragma unroll
    for (int i = 0; i < 4; ++i)
        #pragma unroll
        for (int j = 0; j < 4; ++j)
            #pragma unroll
            for (int r = 0; r < 4; ++r) acc[i][j][r] = 0.f;

    auto load_stage = [&](int s, int k0) {
        __nv_bfloat16* Ah = smem + s * STAGE_ELEMS;
        __nv_bfloat16* Al = Ah + A_TILE;
        __nv_bfloat16* Bh = Al + A_TILE;
        __nv_bfloat16* Bl = Bh + B_TILE;
        #pragma unroll
        for (int c = tid; c < GBM * 4; c += 512) {
            int row = c >> 2, col = (c & 3) * 8;
            size_t g = (size_t)(bm + row) * K + k0 + col;
            cp16(Ah + row * GROW + col, Ah_g + g);
            cp16(Al + row * GROW + col, Al_g + g);
        }
        {
            int c = tid;
            if (c < GBN * 4) {
                int row = c >> 2, col = (c & 3) * 8;
                size_t g = (size_t)(bn + row) * K + k0 + col;
                cp16(Bh + row * GROW + col, Bh_g + g);
                cp16(Bl + row * GROW + col, Bl_g + g);
            }
        }
    };

    const int niter = K / GBK;
    load_stage(0, 0);
    cp_commit();

    for (int it = 0; it < niter; ++it) {
        if (it + 1 < niter) {
            load_stage((it + 1) & 1, (it + 1) * GBK);
            cp_commit();
            cp_wait<1>();
        } else {
            cp_wait<0>();
        }
        __syncthreads();

        const __nv_bfloat16* Ah = smem + (it & 1) * STAGE_ELEMS;
        const __nv_bfloat16* Al = Ah + A_TILE;
        const __nv_bfloat16* Bh = Al + A_TILE;
        const __nv_bfloat16* Bl = Bh + B_TILE;

        #pragma unroll
        for (int kk = 0; kk < GBK; kk += 16) {
            const int arow = wm + (lane & 15);
            const int acol = kk + (lane >> 4) * 8;
            const int brow = wn + (lane & 7);
            const int bcol = kk + ((lane >> 3) & 1) * 8;

            uint32_t afh[4][4], afl[4][4], bfh[4][2], bfl[4][2];
            #pragma unroll
            for (int mt = 0; mt < 4; ++mt)
                ldm_x4(afh[mt], Ah + (arow + mt * 16) * GROW + acol);
            #pragma unroll
            for (int nt = 0; nt < 4; ++nt)
                ldm_x2(bfh[nt], Bh + (brow + nt * 8) * GROW + bcol);

            #pragma unroll
            for (int mt = 0; mt < 4; ++mt)
                #pragma unroll
                for (int nt = 0; nt < 4; ++nt)
                    mma_bf16(acc[mt][nt], afh[mt], bfh[nt]);

            #pragma unroll
            for (int nt = 0; nt < 4; ++nt)
                ldm_x2(bfl[nt], Bl + (brow + nt * 8) * GROW + bcol);
            #pragma unroll
            for (int mt = 0; mt < 4; ++mt)
                #pragma unroll
                for (int nt = 0; nt < 4; ++nt)
                    mma_bf16(acc[mt][nt], afh[mt], bfl[nt]);

            #pragma unroll
            for (int mt = 0; mt < 4; ++mt)
                ldm_x4(afl[mt], Al + (arow + mt * 16) * GROW + acol);
            #pragma unroll
            for (int mt = 0; mt < 4; ++mt)
                #pragma unroll
                for (int nt = 0; nt < 4; ++nt)
                    mma_bf16(acc[mt][nt], afl[mt], bfh[nt]);
        }
        __syncthreads();
    }

    // Epilogue
    #pragma unroll
    for (int mt = 0; mt < 4; ++mt) {
        int r0 = bm + wm + mt * 16 + (lane >> 2);
        #pragma unroll
        for (int nt = 0; nt < 4; ++nt) {
            int cc = bn + wn + nt * 8 + (lane & 3) * 2;
            float b0 = bias[cc], b1 = bias[cc + 1];
            float v0 = acc[mt][nt][0] + b0, v1 = acc[mt][nt][1] + b1;
            float v2 = acc[mt][nt][2] + b0, v3 = acc[mt][nt][3] + b1;
            if (Cf) {
                *(float2*)(Cf + (size_t)r0 * N + cc)       = make_float2(v0, v1);
                *(float2*)(Cf + (size_t)(r0 + 8) * N + cc) = make_float2(v2, v3);
            } else {
                uint32_t h01, l01, h23, l23;
                splitpack2(v0, v1, h01, l01);
                splitpack2(v2, v3, h23, l23);
                *(uint32_t*)(Chi + (size_t)r0 * N + cc)       = h01;
                *(uint32_t*)(Clo + (size_t)r0 * N + cc)       = l01;
                *(uint32_t*)(Chi + (size_t)(r0 + 8) * N + cc) = h23;
                *(uint32_t*)(Clo + (size_t)(r0 + 8) * N + cc) = l23;
            }
        }
    }
}

// ---------------------------------------------------------------------------
// Tensor-core causal flash attention, split-bf16 (3-term QK^T and PV).
// Block = (b, h, 64-q-rows), 128 threads (4 warps x 16 q-rows).
// KV tiles 64 wide, double-buffered cp.async. V consumed via ldmatrix.trans.
// Writes yh/yl (bf16 split) directly for the proj GEMM.
// ---------------------------------------------------------------------------
#define AROW  72                  // 64 + 8 pad (bf16)
#define ATILE (64 * AROW)         // 4608 elems
#define ASTG  (4 * ATILE)         // Kh,Kl,Vh,Vl per stage
#define FLASH_SMEM_BYTES ((2 * ATILE + 2 * ASTG) * 2)   // 92160 B

__global__ __launch_bounds__(128)
void flash_attn_tc(const __nv_bfloat16* __restrict__ qkvh,
                   const __nv_bfloat16* __restrict__ qkvl,
                   __nv_bfloat16* __restrict__ yh,
                   __nv_bfloat16* __restrict__ yl)
{
    extern __shared__ __nv_bfloat16 sm[];
    __nv_bfloat16* Qh = sm;
    __nv_bfloat16* Ql = sm + ATILE;
    __nv_bfloat16* KV = sm + 2 * ATILE;

    const int qb = gridDim.x - 1 - blockIdx.x;   // heavy blocks first
    const int h  = blockIdx.y;
    const int b  = blockIdx.z;
    const int q0 = qb * 64;
    const int tid = threadIdx.x, warp = tid >> 5, lane = tid & 31;

    const size_t rstride = (size_t)3 * CDIM;
    const size_t base = (size_t)b * T_SEQ * rstride + (size_t)h * HD;

    // Q tiles (cp.async, one group)
    for (int i = tid; i < 512; i += 128) {
        int r = i >> 3, ch = i & 7;
        size_t g = base + (size_t)(q0 + r) * rstride + ch * 8;
        cp16(Qh + r * AROW + ch * 8, qkvh + g);
        cp16(Ql + r * AROW + ch * 8, qkvl + g);
    }
    cp_commit();

    auto load_kv = [&](int s, int k0) {
        __nv_bfloat16* Kh = KV + s * ASTG;
        __nv_bfloat16* Kl = Kh + ATILE;
        __nv_bfloat16* Vh = Kl + ATILE;
        __nv_bfloat16* Vl = Vh + ATILE;
        for (int i = tid; i < 512; i += 128) {
            int r = i >> 3, ch = i & 7;
            size_t gk = base + CDIM + (size_t)(k0 + r) * rstride + ch * 8;
            size_t gv = gk + CDIM;
            cp16(Kh + r * AROW + ch * 8, qkvh + gk);
            cp16(Kl + r * AROW + ch * 8, qkvl + gk);
            cp16(Vh + r * AROW + ch * 8, qkvh + gv);
            cp16(Vl + r * AROW + ch * 8, qkvl + gv);
        }
    };
    load_kv(0, 0);
    cp_commit();

    float o[8][4];
    #pragma unroll
    for (int nb = 0; nb < 8; ++nb)
        #pragma unroll
        for (int r = 0; r < 4; ++r) o[nb][r] = 0.f;
    float m0 = -1e30f, m1 = -1e30f, l0 = 0.f, l1 = 0.f;

    const float SC = 0.125f * 1.4426950408889634f;   // (1/sqrt(64))·log2(e)
    const int rin   = lane >> 2;                     // 0..7
    const int qrow0 = q0 + warp * 16 + rin;
    const int qrow1 = qrow0 + 8;
    const int cbase = 2 * (lane & 3);

    for (int kt = 0; kt <= qb; ++kt) {
        cp_wait<0>();
        __syncthreads();
        if (kt < qb) { load_kv((kt + 1) & 1, (kt + 1) * 64); cp_commit(); }

        const __nv_bfloat16* Kh = KV + (kt & 1) * ASTG;
        const __nv_bfloat16* Kl = Kh + ATILE;
        const __nv_bfloat16* Vh = Kl + ATILE;
        const __nv_bfloat16* Vl = Vh + ATILE;

        // ---- S = Q K^T (3-term) ----
        float s[8][4];
        #pragma unroll
        for (int nb = 0; nb < 8; ++nb)
            #pragma unroll
            for (int r = 0; r < 4; ++r) s[nb][r] = 0.f;

        #pragma unroll
        for (int ks = 0; ks < 4; ++ks) {
            const int aoff = (warp * 16 + (lane & 15)) * AROW + ks * 16 + (lane >> 4) * 8;
            uint32_t ah[4], al[4];
            ldm_x4(ah, Qh + aoff);
            ldm_x4(al, Ql + aoff);
            #pragma unroll
            for (int nb = 0; nb < 8; ++nb) {
                const int boff = (nb * 8 + (lane & 7)) * AROW + ks * 16 + ((lane >> 3) & 1) * 8;
                uint32_t bh[2], bl[2];
                ldm_x2(bh, Kh + boff);
                ldm_x2(bl, Kl + boff);
                mma_bf16(s[nb], ah, bh);
                mma_bf16(s[nb], ah, bl);
                mma_bf16(s[nb], al, bh);
            }
        }

        // ---- scale (log2 domain) + causal mask (diagonal tile only) ----
        const int k0 = kt * 64;
        if (kt == qb) {
            #pragma unroll
            for (int nb = 0; nb < 8; ++nb) {
                int c0 = k0 + nb * 8 + cbase;
                s[nb][0] = (c0     <= qrow0) ? s[nb][0] * SC : -1e30f;
                s[nb][1] = (c0 + 1 <= qrow0) ? s[nb][1] * SC : -1e30f;
                s[nb][2] = (c0     <= qrow1) ? s[nb][2] * SC : -1e30f;
                s[nb][3] = (c0 + 1 <= qrow1) ? s[nb][3] * SC : -1e30f;
            }
        } else {
            #pragma unroll
            for (int nb = 0; nb < 8; ++nb)
                #pragma unroll
                for (int r = 0; r < 4; ++r) s[nb][r] *= SC;
        }

        // ---- online softmax ----
        float mx0 = -1e30f, mx1 = -1e30f;
        #pragma unroll
        for (int nb = 0; nb < 8; ++nb) {
            mx0 = fmaxf(mx0, fmaxf(s[nb][0], s[nb][1]));
            mx1 = fmaxf(mx1, fmaxf(s[nb][2], s[nb][3]));
        }
        mx0 = fmaxf(mx0, __shfl_xor_sync(0xffffffffu, mx0, 1));
        mx0 = fmaxf(mx0, __shfl_xor_sync(0xffffffffu, mx0, 2));
        mx1 = fmaxf(mx1, __shfl_xor_sync(0xffffffffu, mx1, 1));
        mx1 = fmaxf(mx1, __shfl_xor_sync(0xffffffffu, mx1, 2));

        float nm0 = fmaxf(m0, mx0), nm1 = fmaxf(m1, mx1);
        float sc0 = exp2f(m0 - nm0), sc1 = exp2f(m1 - nm1);
        m0 = nm0; m1 = nm1;

        float rs0 = 0.f, rs1 = 0.f;
        #pragma unroll
        for (int nb = 0; nb < 8; ++nb) {
            s[nb][0] = exp2f(s[nb][0] - nm0);
            s[nb][1] = exp2f(s[nb][1] - nm0);
            s[nb][2] = exp2f(s[nb][2] - nm1);
            s[nb][3] = exp2f(s[nb][3] - nm1);
            rs0 += s[nb][0] + s[nb][1];
            rs1 += s[nb][2] + s[nb][3];
        }
        rs0 += __shfl_xor_sync(0xffffffffu, rs0, 1);
        rs0 += __shfl_xor_sync(0xffffffffu, rs0, 2);
        rs1 += __shfl_xor_sync(0xffffffffu, rs1, 1);
        rs1 += __shfl_xor_sync(0xffffffffu, rs1, 2);
        l0 = l0 * sc0 + rs0;
        l1 = l1 * sc1 + rs1;

        #pragma unroll
        for (int nb = 0; nb < 8; ++nb) {
            o[nb][0] *= sc0; o[nb][1] *= sc0;
            o[nb][2] *= sc1; o[nb][3] *= sc1;
        }

        // ---- O += P V (3-term), P repacked C-frag -> A-frag in registers ----
        #pragma unroll
        for (int t = 0; t < 4; ++t) {
            uint32_t ph[4], pl[4];
            splitpack2(s[2*t  ][0], s[2*t  ][1], ph[0], pl[0]);
            splitpack2(s[2*t  ][2], s[2*t  ][3], ph[1], pl[1]);
            splitpack2(s[2*t+1][0], s[2*t+1][1], ph[2], pl[2]);
            splitpack2(s[2*t+1][2], s[2*t+1][3], ph[3], pl[3]);
            const int voff = (t * 16 + (lane & 15)) * AROW;
            #pragma unroll
            for (int nb = 0; nb < 8; ++nb) {
                uint32_t bh[2], bl[2];
                ldm_x2t(bh, Vh + voff + nb * 8);
                ldm_x2t(bl, Vl + voff + nb * 8);
                mma_bf16(o[nb], ph, bh);
                mma_bf16(o[nb], ph, bl);
                mma_bf16(o[nb], pl, bh);
            }
        }
    }

    // ---- epilogue: normalize, split to bf16 hi/lo, store ----
    float inv0 = 1.f / l0, inv1 = 1.f / l1;
    const size_t row0 = (size_t)b * T_SEQ + qrow0;
    const size_t row1 = (size_t)b * T_SEQ + qrow1;
    #pragma unroll
    for (int nb = 0; nb < 8; ++nb) {
        int cc = h * HD + nb * 8 + cbase;
        uint32_t h01, l01, h23, l23;
        splitpack2(o[nb][0] * inv0, o[nb][1] * inv0, h01, l01);
        splitpack2(o[nb][2] * inv1, o[nb][3] * inv1, h23, l23);
        *(uint32_t*)(yh + row0 * CDIM + cc) = h01;
        *(uint32_t*)(yl + row0 * CDIM + cc) = l01;
        *(uint32_t*)(yh + row1 * CDIM + cc) = h23;
        *(uint32_t*)(yl + row1 * CDIM + cc) = l23;
    }
}

// ---------------------------------------------------------------------------
// kernel_launch
// ---------------------------------------------------------------------------
extern "C" void kernel_launch(void* const* d_in, const int* in_sizes, int n_in,
                              void* d_out, int out_size)
{
    (void)in_sizes; (void)n_in; (void)out_size;
    const float* x      = (const float*)d_in[0];
    const float* W_attn = (const float*)d_in[1];
    const float* b_attn = (const float*)d_in[2];
    const float* W_proj = (const float*)d_in[3];
    const float* b_proj = (const float*)d_in[4];
    float* out = (float*)d_out;

    __nv_bfloat16 *xh, *xl, *qkvh, *qkvl, *yh, *yl, *wah, *wal, *wph, *wpl;
    cudaGetSymbolAddress((void**)&xh,   g_xh);
    cudaGetSymbolAddress((void**)&xl,   g_xl);
    cudaGetSymbolAddress((void**)&qkvh, g_qkvh);
    cudaGetSymbolAddress((void**)&qkvl, g_qkvl);
    cudaGetSymbolAddress((void**)&yh,   g_yh);
    cudaGetSymbolAddress((void**)&yl,   g_yl);
    cudaGetSymbolAddress((void**)&wah,  g_wah);
    cudaGetSymbolAddress((void**)&wal,  g_wal);
    cudaGetSymbolAddress((void**)&wph,  g_wph);
    cudaGetSymbolAddress((void**)&wpl,  g_wpl);

    cudaFuncSetAttribute(gemm_split_bf16, cudaFuncAttributeMaxDynamicSharedMemorySize,
                         GEMM_SMEM_BYTES);
    cudaFuncSetAttribute(flash_attn_tc, cudaFuncAttributeMaxDynamicSharedMemorySize,
                         FLASH_SMEM_BYTES);

    // 1) split x
    {
        int n4 = MROWS * CDIM / 4;
        split_kernel<<<(n4 + 255) / 256, 256>>>(x, xh, xl, n4);
    }
    // 2) split + transpose weights
    {
        dim3 blk(32, 8);
        split_transpose_kernel<<<dim3(3 * CDIM / 32, CDIM / 32), blk>>>(W_attn, wah, wal, CDIM, 3 * CDIM);
        split_transpose_kernel<<<dim3(CDIM / 32, CDIM / 32), blk>>>(W_proj, wph, wpl, CDIM, CDIM);
    }
    // 3) qkv(hi/lo) = split(x @ W_attn + b_attn)   [8192, 3072] bf16 pair
    {
        dim3 grid(3 * CDIM / GBN, MROWS / GBM);
        gemm_split_bf16<<<grid, 512, GEMM_SMEM_BYTES>>>(xh, xl, wah, wal, b_attn,
                                                        nullptr, qkvh, qkvl,
                                                        MROWS, 3 * CDIM, CDIM);
    }
    // 4) tensor-core flash attention -> yh/yl
    {
        dim3 grid(T_SEQ / 64, NHEAD, BATCH);
        flash_attn_tc<<<grid, 128, FLASH_SMEM_BYTES>>>(qkvh, qkvl, yh, yl);
    }
    // 5) out = y @ W_proj + b_proj   [8192, 1024] fp32
    {
        dim3 grid(CDIM / GBN, MROWS / GBM);
        gemm_split_bf16<<<grid, 512, GEMM_SMEM_BYTES>>>(yh, yl, wph, wpl, b_proj,
                                                        out, nullptr, nullptr,
                                                        MROWS, CDIM, CDIM);
    }
}

// round 7
// speedup vs baseline: 2.8853x; 1.0386x over previous
#include <cuda_runtime.h>
#include <cuda_bf16.h>
#include <math.h>
#include <stdint.h>

// Problem constants
#define BATCH   4
#define T_SEQ   2048
#define CDIM    1024
#define NHEAD   16
#define HD      64
#define MROWS   (BATCH * T_SEQ)  // 8192

// ---------------------------------------------------------------------------
// Scratch (allocation-free rule: __device__ globals)
// ---------------------------------------------------------------------------
__device__ __nv_bfloat16 g_xh[(size_t)MROWS * CDIM];
__device__ __nv_bfloat16 g_xl[(size_t)MROWS * CDIM];
__device__ __nv_bfloat16 g_qkvh[(size_t)MROWS * 3 * CDIM];
__device__ __nv_bfloat16 g_qkvl[(size_t)MROWS * 3 * CDIM];
__device__ __nv_bfloat16 g_yh[(size_t)MROWS * CDIM];
__device__ __nv_bfloat16 g_yl[(size_t)MROWS * CDIM];
__device__ __nv_bfloat16 g_wah[(size_t)3 * CDIM * CDIM];   // W_attn^T hi [3072][1024]
__device__ __nv_bfloat16 g_wal[(size_t)3 * CDIM * CDIM];
__device__ __nv_bfloat16 g_wph[(size_t)CDIM * CDIM];
__device__ __nv_bfloat16 g_wpl[(size_t)CDIM * CDIM];

// ---------------------------------------------------------------------------
// PTX helpers (sm_103-safe set only: cp.async / ldmatrix / mma.sync)
// ---------------------------------------------------------------------------
__device__ __forceinline__ void cp16(void* dst, const void* src) {
    uint32_t d = (uint32_t)__cvta_generic_to_shared(dst);
    asm volatile("cp.async.cg.shared.global [%0], [%1], 16;\n" :: "r"(d), "l"(src));
}
__device__ __forceinline__ void cp_commit() {
    asm volatile("cp.async.commit_group;\n" ::: "memory");
}
template <int N> __device__ __forceinline__ void cp_wait() {
    asm volatile("cp.async.wait_group %0;\n" :: "n"(N) : "memory");
}
__device__ __forceinline__ void ldm_x4(uint32_t* r, const void* p) {
    uint32_t a = (uint32_t)__cvta_generic_to_shared(p);
    asm volatile("ldmatrix.sync.aligned.m8n8.x4.shared.b16 {%0,%1,%2,%3},[%4];\n"
                 : "=r"(r[0]), "=r"(r[1]), "=r"(r[2]), "=r"(r[3]) : "r"(a));
}
__device__ __forceinline__ void ldm_x2(uint32_t* r, const void* p) {
    uint32_t a = (uint32_t)__cvta_generic_to_shared(p);
    asm volatile("ldmatrix.sync.aligned.m8n8.x2.shared.b16 {%0,%1},[%2];\n"
                 : "=r"(r[0]), "=r"(r[1]) : "r"(a));
}
__device__ __forceinline__ void ldm_x2t(uint32_t* r, const void* p) {
    uint32_t a = (uint32_t)__cvta_generic_to_shared(p);
    asm volatile("ldmatrix.sync.aligned.m8n8.x2.trans.shared.b16 {%0,%1},[%2];\n"
                 : "=r"(r[0]), "=r"(r[1]) : "r"(a));
}
__device__ __forceinline__ void mma_bf16(float* c, const uint32_t* a, const uint32_t* b) {
    asm volatile(
        "mma.sync.aligned.m16n8k16.row.col.f32.bf16.bf16.f32 "
        "{%0,%1,%2,%3},{%4,%5,%6,%7},{%8,%9},{%0,%1,%2,%3};\n"
        : "+f"(c[0]), "+f"(c[1]), "+f"(c[2]), "+f"(c[3])
        : "r"(a[0]), "r"(a[1]), "r"(a[2]), "r"(a[3]), "r"(b[0]), "r"(b[1]));
}
__device__ __forceinline__ void splitpack2(float a, float b, uint32_t& hi, uint32_t& lo) {
    __nv_bfloat16 ha = __float2bfloat16_rn(a);
    __nv_bfloat16 hb = __float2bfloat16_rn(b);
    __nv_bfloat16 la = __float2bfloat16_rn(a - __bfloat162float(ha));
    __nv_bfloat16 lb = __float2bfloat16_rn(b - __bfloat162float(hb));
    hi = (uint32_t)(*(uint16_t*)&ha) | ((uint32_t)(*(uint16_t*)&hb) << 16);
    lo = (uint32_t)(*(uint16_t*)&la) | ((uint32_t)(*(uint16_t*)&lb) << 16);
}

// ---------------------------------------------------------------------------
// Split conversion: fp32 -> hi + lo bf16
// ---------------------------------------------------------------------------
__global__ __launch_bounds__(256)
void split_kernel(const float* __restrict__ in, __nv_bfloat16* __restrict__ hi,
                  __nv_bfloat16* __restrict__ lo, int n4)
{
    int i = blockIdx.x * blockDim.x + threadIdx.x;
    if (i >= n4) return;
    float4 v = ((const float4*)in)[i];
    __nv_bfloat16 h[4], l[4];
    float vv[4] = {v.x, v.y, v.z, v.w};
    #pragma unroll
    for (int j = 0; j < 4; ++j) {
        h[j] = __float2bfloat16_rn(vv[j]);
        l[j] = __float2bfloat16_rn(vv[j] - __bfloat162float(h[j]));
    }
    ((uint2*)hi)[i] = *(uint2*)h;
    ((uint2*)lo)[i] = *(uint2*)l;
}

// ---------------------------------------------------------------------------
// Split + transpose: W [K][N] fp32 -> hiT, loT [N][K] bf16
// ---------------------------------------------------------------------------
__global__ __launch_bounds__(256)
void split_transpose_kernel(const float* __restrict__ W,
                            __nv_bfloat16* __restrict__ hiT,
                            __nv_bfloat16* __restrict__ loT, int K, int N)
{
    __shared__ float t[32][33];
    int n0 = blockIdx.x * 32;
    int k0 = blockIdx.y * 32;
    int tx = threadIdx.x, ty = threadIdx.y;   // 32 x 8
    #pragma unroll
    for (int r = 0; r < 32; r += 8)
        t[ty + r][tx] = W[(size_t)(k0 + ty + r) * N + n0 + tx];
    __syncthreads();
    #pragma unroll
    for (int r = 0; r < 32; r += 8) {
        float v = t[tx][ty + r];
        __nv_bfloat16 h = __float2bfloat16_rn(v);
        __nv_bfloat16 l = __float2bfloat16_rn(v - __bfloat162float(h));
        size_t o = (size_t)(n0 + ty + r) * K + k0 + tx;
        hiT[o] = h;
        loT[o] = l;
    }
}

// ---------------------------------------------------------------------------
// Split-bf16 mma.sync GEMM (3-term hh+hl+lh), 3-stage cp.async pipeline.
// C[M][N] = (Ah+Al)[M][K] @ (Bh+Bl)[N][K]^T + bias
// Tile 256x128x32, 512 threads (16 warps, 4x4), warp tile 64x32.
// ---------------------------------------------------------------------------
#define GBM 256
#define GBN 128
#define GBK 32
#define GROW (GBK + 8)                 // padded row: 40 bf16 = 80B
#define A_TILE (GBM * GROW)
#define B_TILE (GBN * GROW)
#define STAGE_ELEMS (2 * A_TILE + 2 * B_TILE)   // 30720 bf16
#define NSTAGE 3
#define GEMM_SMEM_BYTES (NSTAGE * STAGE_ELEMS * 2)   // 184320 B

__global__ __launch_bounds__(512, 1)
void gemm_split_bf16(const __nv_bfloat16* __restrict__ Ah_g,
                     const __nv_bfloat16* __restrict__ Al_g,
                     const __nv_bfloat16* __restrict__ Bh_g,
                     const __nv_bfloat16* __restrict__ Bl_g,
                     const float* __restrict__ bias,
                     float* __restrict__ Cf,
                     __nv_bfloat16* __restrict__ Chi,
                     __nv_bfloat16* __restrict__ Clo,
                     int M, int N, int K)
{
    extern __shared__ __nv_bfloat16 smem[];
    const int tid  = threadIdx.x;
    const int bm   = blockIdx.y * GBM;
    const int bn   = blockIdx.x * GBN;
    const int warp = tid >> 5, lane = tid & 31;
    const int wm   = (warp & 3) * 64;
    const int wn   = (warp >> 2) * 32;

    float acc[4][4][4];
    #pragma unroll
    for (int i = 0; i < 4; ++i)
        #pragma unroll
        for (int j = 0; j < 4; ++j)
            #pragma unroll
            for (int r = 0; r < 4; ++r) acc[i][j][r] = 0.f;

    auto load_stage = [&](int s, int k0) {
        __nv_bfloat16* Ah = smem + s * STAGE_ELEMS;
        __nv_bfloat16* Al = Ah + A_TILE;
        __nv_bfloat16* Bh = Al + A_TILE;
        __nv_bfloat16* Bl = Bh + B_TILE;
        #pragma unroll
        for (int c = tid; c < GBM * 4; c += 512) {
            int row = c >> 2, col = (c & 3) * 8;
            size_t g = (size_t)(bm + row) * K + k0 + col;
            cp16(Ah + row * GROW + col, Ah_g + g);
            cp16(Al + row * GROW + col, Al_g + g);
        }
        {
            int c = tid;
            if (c < GBN * 4) {
                int row = c >> 2, col = (c & 3) * 8;
                size_t g = (size_t)(bn + row) * K + k0 + col;
                cp16(Bh + row * GROW + col, Bh_g + g);
                cp16(Bl + row * GROW + col, Bl_g + g);
            }
        }
    };

    const int niter = K / GBK;
    load_stage(0, 0); cp_commit();
    load_stage(1, GBK); cp_commit();

    int sc_comp = 0, sc_load = 2;   // stage indices mod 3
    for (int it = 0; it < niter; ++it) {
        if (it + 1 < niter) cp_wait<1>(); else cp_wait<0>();
        __syncthreads();

        // prefetch stage it+2 (buffer freed at last iteration's sync)
        if (it + 2 < niter) {
            load_stage(sc_load, (it + 2) * GBK);
            cp_commit();
        }

        const __nv_bfloat16* Ah = smem + sc_comp * STAGE_ELEMS;
        const __nv_bfloat16* Al = Ah + A_TILE;
        const __nv_bfloat16* Bh = Al + A_TILE;
        const __nv_bfloat16* Bl = Bh + B_TILE;

        #pragma unroll
        for (int kk = 0; kk < GBK; kk += 16) {
            const int arow = wm + (lane & 15);
            const int acol = kk + (lane >> 4) * 8;
            const int brow = wn + (lane & 7);
            const int bcol = kk + ((lane >> 3) & 1) * 8;

            uint32_t bfh[4][2], bfl[4][2];
            #pragma unroll
            for (int nt = 0; nt < 4; ++nt) {
                ldm_x2(bfh[nt], Bh + (brow + nt * 8) * GROW + bcol);
                ldm_x2(bfl[nt], Bl + (brow + nt * 8) * GROW + bcol);
            }
            {   // hi-A terms: hh + hl (afh dies before afl is loaded)
                uint32_t afh[4][4];
                #pragma unroll
                for (int mt = 0; mt < 4; ++mt)
                    ldm_x4(afh[mt], Ah + (arow + mt * 16) * GROW + acol);
                #pragma unroll
                for (int mt = 0; mt < 4; ++mt)
                    #pragma unroll
                    for (int nt = 0; nt < 4; ++nt)
                        mma_bf16(acc[mt][nt], afh[mt], bfh[nt]);
                #pragma unroll
                for (int mt = 0; mt < 4; ++mt)
                    #pragma unroll
                    for (int nt = 0; nt < 4; ++nt)
                        mma_bf16(acc[mt][nt], afh[mt], bfl[nt]);
            }
            {   // lo-A term: lh
                uint32_t afl[4][4];
                #pragma unroll
                for (int mt = 0; mt < 4; ++mt)
                    ldm_x4(afl[mt], Al + (arow + mt * 16) * GROW + acol);
                #pragma unroll
                for (int mt = 0; mt < 4; ++mt)
                    #pragma unroll
                    for (int nt = 0; nt < 4; ++nt)
                        mma_bf16(acc[mt][nt], afl[mt], bfh[nt]);
            }
        }
        sc_comp = (sc_comp + 1 == NSTAGE) ? 0 : sc_comp + 1;
        sc_load = (sc_load + 1 == NSTAGE) ? 0 : sc_load + 1;
        __syncthreads();
    }

    // Epilogue: bias + store
    #pragma unroll
    for (int mt = 0; mt < 4; ++mt) {
        int r0 = bm + wm + mt * 16 + (lane >> 2);
        #pragma unroll
        for (int nt = 0; nt < 4; ++nt) {
            int cc = bn + wn + nt * 8 + (lane & 3) * 2;
            float b0 = bias[cc], b1 = bias[cc + 1];
            float v0 = acc[mt][nt][0] + b0, v1 = acc[mt][nt][1] + b1;
            float v2 = acc[mt][nt][2] + b0, v3 = acc[mt][nt][3] + b1;
            if (Cf) {
                *(float2*)(Cf + (size_t)r0 * N + cc)       = make_float2(v0, v1);
                *(float2*)(Cf + (size_t)(r0 + 8) * N + cc) = make_float2(v2, v3);
            } else {
                uint32_t h01, l01, h23, l23;
                splitpack2(v0, v1, h01, l01);
                splitpack2(v2, v3, h23, l23);
                *(uint32_t*)(Chi + (size_t)r0 * N + cc)       = h01;
                *(uint32_t*)(Clo + (size_t)r0 * N + cc)       = l01;
                *(uint32_t*)(Chi + (size_t)(r0 + 8) * N + cc) = h23;
                *(uint32_t*)(Clo + (size_t)(r0 + 8) * N + cc) = l23;
            }
        }
    }
}

// ---------------------------------------------------------------------------
// Tensor-core causal flash attention, split-bf16, BQ=128 (8 warps, 256 thr).
// KV tiles 64 wide, double-buffered cp.async, V via ldmatrix.trans.
// ---------------------------------------------------------------------------
#define AROW  72
#define QTILE (128 * AROW)       // 9216 elems per (h|l)
#define KTILE (64 * AROW)        // 4608
#define ASTG  (4 * KTILE)        // Kh,Kl,Vh,Vl per stage
#define FLASH_SMEM_BYTES ((2 * QTILE + 2 * ASTG) * 2)   // 110592 B

__global__ __launch_bounds__(256)
void flash_attn_tc(const __nv_bfloat16* __restrict__ qkvh,
                   const __nv_bfloat16* __restrict__ qkvl,
                   __nv_bfloat16* __restrict__ yh,
                   __nv_bfloat16* __restrict__ yl)
{
    extern __shared__ __nv_bfloat16 sm[];
    __nv_bfloat16* Qh = sm;
    __nv_bfloat16* Ql = sm + QTILE;
    __nv_bfloat16* KV = sm + 2 * QTILE;

    const int qb = gridDim.x - 1 - blockIdx.x;   // heavy blocks first
    const int h  = blockIdx.y;
    const int b  = blockIdx.z;
    const int q0 = qb * 128;
    const int tid = threadIdx.x, warp = tid >> 5, lane = tid & 31;

    const size_t rstride = (size_t)3 * CDIM;
    const size_t base = (size_t)b * T_SEQ * rstride + (size_t)h * HD;

    // Q tiles (cp.async, one group)
    for (int i = tid; i < 1024; i += 256) {
        int r = i >> 3, ch = i & 7;
        size_t g = base + (size_t)(q0 + r) * rstride + ch * 8;
        cp16(Qh + r * AROW + ch * 8, qkvh + g);
        cp16(Ql + r * AROW + ch * 8, qkvl + g);
    }
    cp_commit();

    auto load_kv = [&](int s, int k0) {
        __nv_bfloat16* Kh = KV + s * ASTG;
        __nv_bfloat16* Kl = Kh + KTILE;
        __nv_bfloat16* Vh = Kl + KTILE;
        __nv_bfloat16* Vl = Vh + KTILE;
        for (int i = tid; i < 512; i += 256) {
            int r = i >> 3, ch = i & 7;
            size_t gk = base + CDIM + (size_t)(k0 + r) * rstride + ch * 8;
            size_t gv = gk + CDIM;
            cp16(Kh + r * AROW + ch * 8, qkvh + gk);
            cp16(Kl + r * AROW + ch * 8, qkvl + gk);
            cp16(Vh + r * AROW + ch * 8, qkvh + gv);
            cp16(Vl + r * AROW + ch * 8, qkvl + gv);
        }
    };
    load_kv(0, 0);
    cp_commit();

    float o[8][4];
    #pragma unroll
    for (int nb = 0; nb < 8; ++nb)
        #pragma unroll
        for (int r = 0; r < 4; ++r) o[nb][r] = 0.f;
    float m0 = -1e30f, m1 = -1e30f, l0 = 0.f, l1 = 0.f;

    const float SC = 0.125f * 1.4426950408889634f;   // (1/sqrt(64))·log2(e)
    const int rin   = lane >> 2;
    const int qrow0 = q0 + warp * 16 + rin;
    const int qrow1 = qrow0 + 8;
    const int cbase = 2 * (lane & 3);

    const int nkt = 2 * qb + 2;
    for (int kt = 0; kt < nkt; ++kt) {
        cp_wait<0>();
        __syncthreads();
        if (kt + 1 < nkt) { load_kv((kt + 1) & 1, (kt + 1) * 64); cp_commit(); }

        const __nv_bfloat16* Kh = KV + (kt & 1) * ASTG;
        const __nv_bfloat16* Kl = Kh + KTILE;
        const __nv_bfloat16* Vh = Kl + KTILE;
        const __nv_bfloat16* Vl = Vh + KTILE;

        // ---- S = Q K^T (3-term) ----
        float s[8][4];
        #pragma unroll
        for (int nb = 0; nb < 8; ++nb)
            #pragma unroll
            for (int r = 0; r < 4; ++r) s[nb][r] = 0.f;

        #pragma unroll
        for (int ks = 0; ks < 4; ++ks) {
            const int aoff = (warp * 16 + (lane & 15)) * AROW + ks * 16 + (lane >> 4) * 8;
            uint32_t ah[4], al[4];
            ldm_x4(ah, Qh + aoff);
            ldm_x4(al, Ql + aoff);
            #pragma unroll
            for (int nb = 0; nb < 8; ++nb) {
                const int boff = (nb * 8 + (lane & 7)) * AROW + ks * 16 + ((lane >> 3) & 1) * 8;
                uint32_t bh[2], bl[2];
                ldm_x2(bh, Kh + boff);
                ldm_x2(bl, Kl + boff);
                mma_bf16(s[nb], ah, bh);
                mma_bf16(s[nb], ah, bl);
                mma_bf16(s[nb], al, bh);
            }
        }

        // ---- scale (log2 domain) + causal mask on diagonal tiles ----
        const int k0 = kt * 64;
        if (kt >= 2 * qb) {
            #pragma unroll
            for (int nb = 0; nb < 8; ++nb) {
                int c0 = k0 + nb * 8 + cbase;
                s[nb][0] = (c0     <= qrow0) ? s[nb][0] * SC : -1e30f;
                s[nb][1] = (c0 + 1 <= qrow0) ? s[nb][1] * SC : -1e30f;
                s[nb][2] = (c0     <= qrow1) ? s[nb][2] * SC : -1e30f;
                s[nb][3] = (c0 + 1 <= qrow1) ? s[nb][3] * SC : -1e30f;
            }
        } else {
            #pragma unroll
            for (int nb = 0; nb < 8; ++nb)
                #pragma unroll
                for (int r = 0; r < 4; ++r) s[nb][r] *= SC;
        }

        // ---- online softmax ----
        float mx0 = -1e30f, mx1 = -1e30f;
        #pragma unroll
        for (int nb = 0; nb < 8; ++nb) {
            mx0 = fmaxf(mx0, fmaxf(s[nb][0], s[nb][1]));
            mx1 = fmaxf(mx1, fmaxf(s[nb][2], s[nb][3]));
        }
        mx0 = fmaxf(mx0, __shfl_xor_sync(0xffffffffu, mx0, 1));
        mx0 = fmaxf(mx0, __shfl_xor_sync(0xffffffffu, mx0, 2));
        mx1 = fmaxf(mx1, __shfl_xor_sync(0xffffffffu, mx1, 1));
        mx1 = fmaxf(mx1, __shfl_xor_sync(0xffffffffu, mx1, 2));

        float nm0 = fmaxf(m0, mx0), nm1 = fmaxf(m1, mx1);
        float sc0 = exp2f(m0 - nm0), sc1 = exp2f(m1 - nm1);
        m0 = nm0; m1 = nm1;

        float rs0 = 0.f, rs1 = 0.f;
        #pragma unroll
        for (int nb = 0; nb < 8; ++nb) {
            s[nb][0] = exp2f(s[nb][0] - nm0);
            s[nb][1] = exp2f(s[nb][1] - nm0);
            s[nb][2] = exp2f(s[nb][2] - nm1);
            s[nb][3] = exp2f(s[nb][3] - nm1);
            rs0 += s[nb][0] + s[nb][1];
            rs1 += s[nb][2] + s[nb][3];
        }
        rs0 += __shfl_xor_sync(0xffffffffu, rs0, 1);
        rs0 += __shfl_xor_sync(0xffffffffu, rs0, 2);
        rs1 += __shfl_xor_sync(0xffffffffu, rs1, 1);
        rs1 += __shfl_xor_sync(0xffffffffu, rs1, 2);
        l0 = l0 * sc0 + rs0;
        l1 = l1 * sc1 + rs1;

        #pragma unroll
        for (int nb = 0; nb < 8; ++nb) {
            o[nb][0] *= sc0; o[nb][1] *= sc0;
            o[nb][2] *= sc1; o[nb][3] *= sc1;
        }

        // ---- O += P V (3-term), P repacked C-frag -> A-frag in registers ----
        #pragma unroll
        for (int t = 0; t < 4; ++t) {
            uint32_t ph[4], pl[4];
            splitpack2(s[2*t  ][0], s[2*t  ][1], ph[0], pl[0]);
            splitpack2(s[2*t  ][2], s[2*t  ][3], ph[1], pl[1]);
            splitpack2(s[2*t+1][0], s[2*t+1][1], ph[2], pl[2]);
            splitpack2(s[2*t+1][2], s[2*t+1][3], ph[3], pl[3]);
            const int voff = (t * 16 + (lane & 15)) * AROW;
            #pragma unroll
            for (int nb = 0; nb < 8; ++nb) {
                uint32_t bh[2], bl[2];
                ldm_x2t(bh, Vh + voff + nb * 8);
                ldm_x2t(bl, Vl + voff + nb * 8);
                mma_bf16(o[nb], ph, bh);
                mma_bf16(o[nb], ph, bl);
                mma_bf16(o[nb], pl, bh);
            }
        }
    }

    // ---- epilogue: normalize, split to bf16 hi/lo, store ----
    float inv0 = 1.f / l0, inv1 = 1.f / l1;
    const size_t row0 = (size_t)b * T_SEQ + qrow0;
    const size_t row1 = (size_t)b * T_SEQ + qrow1;
    #pragma unroll
    for (int nb = 0; nb < 8; ++nb) {
        int cc = h * HD + nb * 8 + cbase;
        uint32_t h01, l01, h23, l23;
        splitpack2(o[nb][0] * inv0, o[nb][1] * inv0, h01, l01);
        splitpack2(o[nb][2] * inv1, o[nb][3] * inv1, h23, l23);
        *(uint32_t*)(yh + row0 * CDIM + cc) = h01;
        *(uint32_t*)(yl + row0 * CDIM + cc) = l01;
        *(uint32_t*)(yh + row1 * CDIM + cc) = h23;
        *(uint32_t*)(yl + row1 * CDIM + cc) = l23;
    }
}

// ---------------------------------------------------------------------------
// kernel_launch
// ---------------------------------------------------------------------------
extern "C" void kernel_launch(void* const* d_in, const int* in_sizes, int n_in,
                              void* d_out, int out_size)
{
    (void)in_sizes; (void)n_in; (void)out_size;
    const float* x      = (const float*)d_in[0];
    const float* W_attn = (const float*)d_in[1];
    const float* b_attn = (const float*)d_in[2];
    const float* W_proj = (const float*)d_in[3];
    const float* b_proj = (const float*)d_in[4];
    float* out = (float*)d_out;

    __nv_bfloat16 *xh, *xl, *qkvh, *qkvl, *yh, *yl, *wah, *wal, *wph, *wpl;
    cudaGetSymbolAddress((void**)&xh,   g_xh);
    cudaGetSymbolAddress((void**)&xl,   g_xl);
    cudaGetSymbolAddress((void**)&qkvh, g_qkvh);
    cudaGetSymbolAddress((void**)&qkvl, g_qkvl);
    cudaGetSymbolAddress((void**)&yh,   g_yh);
    cudaGetSymbolAddress((void**)&yl,   g_yl);
    cudaGetSymbolAddress((void**)&wah,  g_wah);
    cudaGetSymbolAddress((void**)&wal,  g_wal);
    cudaGetSymbolAddress((void**)&wph,  g_wph);
    cudaGetSymbolAddress((void**)&wpl,  g_wpl);

    cudaFuncSetAttribute(gemm_split_bf16, cudaFuncAttributeMaxDynamicSharedMemorySize,
                         GEMM_SMEM_BYTES);
    cudaFuncSetAttribute(flash_attn_tc, cudaFuncAttributeMaxDynamicSharedMemorySize,
                         FLASH_SMEM_BYTES);

    // 1) split x
    {
        int n4 = MROWS * CDIM / 4;
        split_kernel<<<(n4 + 255) / 256, 256>>>(x, xh, xl, n4);
    }
    // 2) split + transpose weights
    {
        dim3 blk(32, 8);
        split_transpose_kernel<<<dim3(3 * CDIM / 32, CDIM / 32), blk>>>(W_attn, wah, wal, CDIM, 3 * CDIM);
        split_transpose_kernel<<<dim3(CDIM / 32, CDIM / 32), blk>>>(W_proj, wph, wpl, CDIM, CDIM);
    }
    // 3) qkv(hi/lo) = split(x @ W_attn + b_attn)   [8192, 3072]
    {
        dim3 grid(3 * CDIM / GBN, MROWS / GBM);
        gemm_split_bf16<<<grid, 512, GEMM_SMEM_BYTES>>>(xh, xl, wah, wal, b_attn,
                                                        nullptr, qkvh, qkvl,
                                                        MROWS, 3 * CDIM, CDIM);
    }
    // 4) tensor-core flash attention -> yh/yl  (BQ=128)
    {
        dim3 grid(T_SEQ / 128, NHEAD, BATCH);
        flash_attn_tc<<<grid, 256, FLASH_SMEM_BYTES>>>(qkvh, qkvl, yh, yl);
    }
    // 5) out = y @ W_proj + b_proj   [8192, 1024] fp32
    {
        dim3 grid(CDIM / GBN, MROWS / GBM);
        gemm_split_bf16<<<grid, 512, GEMM_SMEM_BYTES>>>(yh, yl, wph, wpl, b_proj,
                                                        out, nullptr, nullptr,
                                                        MROWS, CDIM, CDIM);
    }
}

// round 8
// speedup vs baseline: 3.0960x; 1.0730x over previous
#include <cuda_runtime.h>
#include <cuda_bf16.h>
#include <math.h>
#include <stdint.h>

// Problem constants
#define BATCH   4
#define T_SEQ   2048
#define CDIM    1024
#define NHEAD   16
#define HD      64
#define MROWS   (BATCH * T_SEQ)  // 8192

// ---------------------------------------------------------------------------
// Scratch (allocation-free rule: __device__ globals)
// ---------------------------------------------------------------------------
__device__ __nv_bfloat16 g_xh[(size_t)MROWS * CDIM];
__device__ __nv_bfloat16 g_xl[(size_t)MROWS * CDIM];
__device__ __nv_bfloat16 g_qkvh[(size_t)MROWS * 3 * CDIM];
__device__ __nv_bfloat16 g_qkvl[(size_t)MROWS * 3 * CDIM];
__device__ __nv_bfloat16 g_yh[(size_t)MROWS * CDIM];
__device__ __nv_bfloat16 g_yl[(size_t)MROWS * CDIM];
__device__ __nv_bfloat16 g_wah[(size_t)3 * CDIM * CDIM];   // W_attn^T hi [3072][1024]
__device__ __nv_bfloat16 g_wal[(size_t)3 * CDIM * CDIM];
__device__ __nv_bfloat16 g_wph[(size_t)CDIM * CDIM];
__device__ __nv_bfloat16 g_wpl[(size_t)CDIM * CDIM];

// ---------------------------------------------------------------------------
// PTX helpers (sm_103-safe set only: cp.async / ldmatrix / mma.sync)
// ---------------------------------------------------------------------------
__device__ __forceinline__ void cp16(void* dst, const void* src) {
    uint32_t d = (uint32_t)__cvta_generic_to_shared(dst);
    asm volatile("cp.async.cg.shared.global [%0], [%1], 16;\n" :: "r"(d), "l"(src));
}
__device__ __forceinline__ void cp_commit() {
    asm volatile("cp.async.commit_group;\n" ::: "memory");
}
template <int N> __device__ __forceinline__ void cp_wait() {
    asm volatile("cp.async.wait_group %0;\n" :: "n"(N) : "memory");
}
__device__ __forceinline__ void ldm_x4(uint32_t* r, const void* p) {
    uint32_t a = (uint32_t)__cvta_generic_to_shared(p);
    asm volatile("ldmatrix.sync.aligned.m8n8.x4.shared.b16 {%0,%1,%2,%3},[%4];\n"
                 : "=r"(r[0]), "=r"(r[1]), "=r"(r[2]), "=r"(r[3]) : "r"(a));
}
__device__ __forceinline__ void ldm_x2(uint32_t* r, const void* p) {
    uint32_t a = (uint32_t)__cvta_generic_to_shared(p);
    asm volatile("ldmatrix.sync.aligned.m8n8.x2.shared.b16 {%0,%1},[%2];\n"
                 : "=r"(r[0]), "=r"(r[1]) : "r"(a));
}
__device__ __forceinline__ void ldm_x2t(uint32_t* r, const void* p) {
    uint32_t a = (uint32_t)__cvta_generic_to_shared(p);
    asm volatile("ldmatrix.sync.aligned.m8n8.x2.trans.shared.b16 {%0,%1},[%2];\n"
                 : "=r"(r[0]), "=r"(r[1]) : "r"(a));
}
__device__ __forceinline__ void mma_bf16(float* c, const uint32_t* a, const uint32_t* b) {
    asm volatile(
        "mma.sync.aligned.m16n8k16.row.col.f32.bf16.bf16.f32 "
        "{%0,%1,%2,%3},{%4,%5,%6,%7},{%8,%9},{%0,%1,%2,%3};\n"
        : "+f"(c[0]), "+f"(c[1]), "+f"(c[2]), "+f"(c[3])
        : "r"(a[0]), "r"(a[1]), "r"(a[2]), "r"(a[3]), "r"(b[0]), "r"(b[1]));
}
__device__ __forceinline__ void splitpack2(float a, float b, uint32_t& hi, uint32_t& lo) {
    __nv_bfloat16 ha = __float2bfloat16_rn(a);
    __nv_bfloat16 hb = __float2bfloat16_rn(b);
    __nv_bfloat16 la = __float2bfloat16_rn(a - __bfloat162float(ha));
    __nv_bfloat16 lb = __float2bfloat16_rn(b - __bfloat162float(hb));
    hi = (uint32_t)(*(uint16_t*)&ha) | ((uint32_t)(*(uint16_t*)&hb) << 16);
    lo = (uint32_t)(*(uint16_t*)&la) | ((uint32_t)(*(uint16_t*)&lb) << 16);
}

// ---------------------------------------------------------------------------
// Split conversion: fp32 -> hi + lo bf16
// ---------------------------------------------------------------------------
__global__ __launch_bounds__(256)
void split_kernel(const float* __restrict__ in, __nv_bfloat16* __restrict__ hi,
                  __nv_bfloat16* __restrict__ lo, int n4)
{
    int i = blockIdx.x * blockDim.x + threadIdx.x;
    if (i >= n4) return;
    float4 v = ((const float4*)in)[i];
    __nv_bfloat16 h[4], l[4];
    float vv[4] = {v.x, v.y, v.z, v.w};
    #pragma unroll
    for (int j = 0; j < 4; ++j) {
        h[j] = __float2bfloat16_rn(vv[j]);
        l[j] = __float2bfloat16_rn(vv[j] - __bfloat162float(h[j]));
    }
    ((uint2*)hi)[i] = *(uint2*)h;
    ((uint2*)lo)[i] = *(uint2*)l;
}

// ---------------------------------------------------------------------------
// Split + transpose: W [K][N] fp32 -> hiT, loT [N][K] bf16
// ---------------------------------------------------------------------------
__global__ __launch_bounds__(256)
void split_transpose_kernel(const float* __restrict__ W,
                            __nv_bfloat16* __restrict__ hiT,
                            __nv_bfloat16* __restrict__ loT, int K, int N)
{
    __shared__ float t[32][33];
    int n0 = blockIdx.x * 32;
    int k0 = blockIdx.y * 32;
    int tx = threadIdx.x, ty = threadIdx.y;   // 32 x 8
    #pragma unroll
    for (int r = 0; r < 32; r += 8)
        t[ty + r][tx] = W[(size_t)(k0 + ty + r) * N + n0 + tx];
    __syncthreads();
    #pragma unroll
    for (int r = 0; r < 32; r += 8) {
        float v = t[tx][ty + r];
        __nv_bfloat16 h = __float2bfloat16_rn(v);
        __nv_bfloat16 l = __float2bfloat16_rn(v - __bfloat162float(h));
        size_t o = (size_t)(n0 + ty + r) * K + k0 + tx;
        hiT[o] = h;
        loT[o] = l;
    }
}

// ---------------------------------------------------------------------------
// Split-bf16 mma.sync GEMM (3-term hh+hl+lh), 2-stage cp.async pipeline.
// C[M][N] = (Ah+Al)[M][K] @ (Bh+Bl)[N][K]^T + bias
// Tile 128x128x32, 256 threads (8 warps, 2m x 4n), warp tile 64x32.
// 2 CTAs/SM (regs < 128/thread, 80KB smem/CTA) so barriers overlap.
// ---------------------------------------------------------------------------
#define GBM 128
#define GBN 128
#define GBK 32
#define GROW (GBK + 8)                 // padded row: 40 bf16 = 80B
#define A_TILE (GBM * GROW)            // 5120 bf16
#define B_TILE (GBN * GROW)            // 5120 bf16
#define STAGE_ELEMS (2 * A_TILE + 2 * B_TILE)   // 20480 bf16
#define GEMM_SMEM_BYTES (2 * STAGE_ELEMS * 2)   // 81920 B

__global__ __launch_bounds__(256, 2)
void gemm_split_bf16(const __nv_bfloat16* __restrict__ Ah_g,
                     const __nv_bfloat16* __restrict__ Al_g,
                     const __nv_bfloat16* __restrict__ Bh_g,
                     const __nv_bfloat16* __restrict__ Bl_g,
                     const float* __restrict__ bias,
                     float* __restrict__ Cf,
                     __nv_bfloat16* __restrict__ Chi,
                     __nv_bfloat16* __restrict__ Clo,
                     int M, int N, int K)
{
    extern __shared__ __nv_bfloat16 smem[];
    const int tid  = threadIdx.x;
    const int bm   = blockIdx.y * GBM;
    const int bn   = blockIdx.x * GBN;
    const int warp = tid >> 5, lane = tid & 31;
    const int wm   = (warp & 1) * 64;
    const int wn   = (warp >> 1) * 32;

    float acc[4][4][4];
    #pragma unroll
    for (int i = 0; i < 4; ++i)
        #pragma unroll
        for (int j = 0; j < 4; ++j)
            #pragma unroll
            for (int r = 0; r < 4; ++r) acc[i][j][r] = 0.f;

    auto load_stage = [&](int s, int k0) {
        __nv_bfloat16* Ah = smem + s * STAGE_ELEMS;
        __nv_bfloat16* Al = Ah + A_TILE;
        __nv_bfloat16* Bh = Al + A_TILE;
        __nv_bfloat16* Bl = Bh + B_TILE;
        #pragma unroll
        for (int c = tid; c < GBM * 4; c += 256) {
            int row = c >> 2, col = (c & 3) * 8;
            size_t ga = (size_t)(bm + row) * K + k0 + col;
            size_t gb = (size_t)(bn + row) * K + k0 + col;
            cp16(Ah + row * GROW + col, Ah_g + ga);
            cp16(Al + row * GROW + col, Al_g + ga);
            cp16(Bh + row * GROW + col, Bh_g + gb);
            cp16(Bl + row * GROW + col, Bl_g + gb);
        }
    };

    const int niter = K / GBK;
    load_stage(0, 0);
    cp_commit();

    for (int it = 0; it < niter; ++it) {
        if (it + 1 < niter) {
            load_stage((it + 1) & 1, (it + 1) * GBK);
            cp_commit();
            cp_wait<1>();
        } else {
            cp_wait<0>();
        }
        __syncthreads();

        const __nv_bfloat16* Ah = smem + (it & 1) * STAGE_ELEMS;
        const __nv_bfloat16* Al = Ah + A_TILE;
        const __nv_bfloat16* Bh = Al + A_TILE;
        const __nv_bfloat16* Bl = Bh + B_TILE;

        #pragma unroll
        for (int kk = 0; kk < GBK; kk += 16) {
            const int arow = wm + (lane & 15);
            const int acol = kk + (lane >> 4) * 8;
            const int brow = wn + (lane & 7);
            const int bcol = kk + ((lane >> 3) & 1) * 8;

            uint32_t bfh[4][2], bfl[4][2];
            #pragma unroll
            for (int nt = 0; nt < 4; ++nt) {
                ldm_x2(bfh[nt], Bh + (brow + nt * 8) * GROW + bcol);
                ldm_x2(bfl[nt], Bl + (brow + nt * 8) * GROW + bcol);
            }
            {   // hi-A terms: hh + hl
                uint32_t afh[4][4];
                #pragma unroll
                for (int mt = 0; mt < 4; ++mt)
                    ldm_x4(afh[mt], Ah + (arow + mt * 16) * GROW + acol);
                #pragma unroll
                for (int mt = 0; mt < 4; ++mt)
                    #pragma unroll
                    for (int nt = 0; nt < 4; ++nt)
                        mma_bf16(acc[mt][nt], afh[mt], bfh[nt]);
                #pragma unroll
                for (int mt = 0; mt < 4; ++mt)
                    #pragma unroll
                    for (int nt = 0; nt < 4; ++nt)
                        mma_bf16(acc[mt][nt], afh[mt], bfl[nt]);
            }
            {   // lo-A term: lh
                uint32_t afl[4][4];
                #pragma unroll
                for (int mt = 0; mt < 4; ++mt)
                    ldm_x4(afl[mt], Al + (arow + mt * 16) * GROW + acol);
                #pragma unroll
                for (int mt = 0; mt < 4; ++mt)
                    #pragma unroll
                    for (int nt = 0; nt < 4; ++nt)
                        mma_bf16(acc[mt][nt], afl[mt], bfh[nt]);
            }
        }
        __syncthreads();
    }

    // Epilogue: bias + store
    #pragma unroll
    for (int mt = 0; mt < 4; ++mt) {
        int r0 = bm + wm + mt * 16 + (lane >> 2);
        #pragma unroll
        for (int nt = 0; nt < 4; ++nt) {
            int cc = bn + wn + nt * 8 + (lane & 3) * 2;
            float b0 = bias[cc], b1 = bias[cc + 1];
            float v0 = acc[mt][nt][0] + b0, v1 = acc[mt][nt][1] + b1;
            float v2 = acc[mt][nt][2] + b0, v3 = acc[mt][nt][3] + b1;
            if (Cf) {
                *(float2*)(Cf + (size_t)r0 * N + cc)       = make_float2(v0, v1);
                *(float2*)(Cf + (size_t)(r0 + 8) * N + cc) = make_float2(v2, v3);
            } else {
                uint32_t h01, l01, h23, l23;
                splitpack2(v0, v1, h01, l01);
                splitpack2(v2, v3, h23, l23);
                *(uint32_t*)(Chi + (size_t)r0 * N + cc)       = h01;
                *(uint32_t*)(Clo + (size_t)r0 * N + cc)       = l01;
                *(uint32_t*)(Chi + (size_t)(r0 + 8) * N + cc) = h23;
                *(uint32_t*)(Clo + (size_t)(r0 + 8) * N + cc) = l23;
            }
        }
    }
}

// ---------------------------------------------------------------------------
// Tensor-core causal flash attention, split-bf16, BQ=128 (8 warps, 256 thr).
// (unchanged from R6 passing version)
// ---------------------------------------------------------------------------
#define AROW  72
#define QTILE (128 * AROW)
#define KTILE (64 * AROW)
#define ASTG  (4 * KTILE)
#define FLASH_SMEM_BYTES ((2 * QTILE + 2 * ASTG) * 2)   // 110592 B

__global__ __launch_bounds__(256)
void flash_attn_tc(const __nv_bfloat16* __restrict__ qkvh,
                   const __nv_bfloat16* __restrict__ qkvl,
                   __nv_bfloat16* __restrict__ yh,
                   __nv_bfloat16* __restrict__ yl)
{
    extern __shared__ __nv_bfloat16 sm[];
    __nv_bfloat16* Qh = sm;
    __nv_bfloat16* Ql = sm + QTILE;
    __nv_bfloat16* KV = sm + 2 * QTILE;

    const int qb = gridDim.x - 1 - blockIdx.x;
    const int h  = blockIdx.y;
    const int b  = blockIdx.z;
    const int q0 = qb * 128;
    const int tid = threadIdx.x, warp = tid >> 5, lane = tid & 31;

    const size_t rstride = (size_t)3 * CDIM;
    const size_t base = (size_t)b * T_SEQ * rstride + (size_t)h * HD;

    for (int i = tid; i < 1024; i += 256) {
        int r = i >> 3, ch = i & 7;
        size_t g = base + (size_t)(q0 + r) * rstride + ch * 8;
        cp16(Qh + r * AROW + ch * 8, qkvh + g);
        cp16(Ql + r * AROW + ch * 8, qkvl + g);
    }
    cp_commit();

    auto load_kv = [&](int s, int k0) {
        __nv_bfloat16* Kh = KV + s * ASTG;
        __nv_bfloat16* Kl = Kh + KTILE;
        __nv_bfloat16* Vh = Kl + KTILE;
        __nv_bfloat16* Vl = Vh + KTILE;
        for (int i = tid; i < 512; i += 256) {
            int r = i >> 3, ch = i & 7;
            size_t gk = base + CDIM + (size_t)(k0 + r) * rstride + ch * 8;
            size_t gv = gk + CDIM;
            cp16(Kh + r * AROW + ch * 8, qkvh + gk);
            cp16(Kl + r * AROW + ch * 8, qkvl + gk);
            cp16(Vh + r * AROW + ch * 8, qkvh + gv);
            cp16(Vl + r * AROW + ch * 8, qkvl + gv);
        }
    };
    load_kv(0, 0);
    cp_commit();

    float o[8][4];
    #pragma unroll
    for (int nb = 0; nb < 8; ++nb)
        #pragma unroll
        for (int r = 0; r < 4; ++r) o[nb][r] = 0.f;
    float m0 = -1e30f, m1 = -1e30f, l0 = 0.f, l1 = 0.f;

    const float SC = 0.125f * 1.4426950408889634f;
    const int rin   = lane >> 2;
    const int qrow0 = q0 + warp * 16 + rin;
    const int qrow1 = qrow0 + 8;
    const int cbase = 2 * (lane & 3);

    const int nkt = 2 * qb + 2;
    for (int kt = 0; kt < nkt; ++kt) {
        cp_wait<0>();
        __syncthreads();
        if (kt + 1 < nkt) { load_kv((kt + 1) & 1, (kt + 1) * 64); cp_commit(); }

        const __nv_bfloat16* Kh = KV + (kt & 1) * ASTG;
        const __nv_bfloat16* Kl = Kh + KTILE;
        const __nv_bfloat16* Vh = Kl + KTILE;
        const __nv_bfloat16* Vl = Vh + KTILE;

        float s[8][4];
        #pragma unroll
        for (int nb = 0; nb < 8; ++nb)
            #pragma unroll
            for (int r = 0; r < 4; ++r) s[nb][r] = 0.f;

        #pragma unroll
        for (int ks = 0; ks < 4; ++ks) {
            const int aoff = (warp * 16 + (lane & 15)) * AROW + ks * 16 + (lane >> 4) * 8;
            uint32_t ah[4], al[4];
            ldm_x4(ah, Qh + aoff);
            ldm_x4(al, Ql + aoff);
            #pragma unroll
            for (int nb = 0; nb < 8; ++nb) {
                const int boff = (nb * 8 + (lane & 7)) * AROW + ks * 16 + ((lane >> 3) & 1) * 8;
                uint32_t bh[2], bl[2];
                ldm_x2(bh, Kh + boff);
                ldm_x2(bl, Kl + boff);
                mma_bf16(s[nb], ah, bh);
                mma_bf16(s[nb], ah, bl);
                mma_bf16(s[nb], al, bh);
            }
        }

        const int k0 = kt * 64;
        if (kt >= 2 * qb) {
            #pragma unroll
            for (int nb = 0; nb < 8; ++nb) {
                int c0 = k0 + nb * 8 + cbase;
                s[nb][0] = (c0     <= qrow0) ? s[nb][0] * SC : -1e30f;
                s[nb][1] = (c0 + 1 <= qrow0) ? s[nb][1] * SC : -1e30f;
                s[nb][2] = (c0     <= qrow1) ? s[nb][2] * SC : -1e30f;
                s[nb][3] = (c0 + 1 <= qrow1) ? s[nb][3] * SC : -1e30f;
            }
        } else {
            #pragma unroll
            for (int nb = 0; nb < 8; ++nb)
                #pragma unroll
                for (int r = 0; r < 4; ++r) s[nb][r] *= SC;
        }

        float mx0 = -1e30f, mx1 = -1e30f;
        #pragma unroll
        for (int nb = 0; nb < 8; ++nb) {
            mx0 = fmaxf(mx0, fmaxf(s[nb][0], s[nb][1]));
            mx1 = fmaxf(mx1, fmaxf(s[nb][2], s[nb][3]));
        }
        mx0 = fmaxf(mx0, __shfl_xor_sync(0xffffffffu, mx0, 1));
        mx0 = fmaxf(mx0, __shfl_xor_sync(0xffffffffu, mx0, 2));
        mx1 = fmaxf(mx1, __shfl_xor_sync(0xffffffffu, mx1, 1));
        mx1 = fmaxf(mx1, __shfl_xor_sync(0xffffffffu, mx1, 2));

        float nm0 = fmaxf(m0, mx0), nm1 = fmaxf(m1, mx1);
        float sc0 = exp2f(m0 - nm0), sc1 = exp2f(m1 - nm1);
        m0 = nm0; m1 = nm1;

        float rs0 = 0.f, rs1 = 0.f;
        #pragma unroll
        for (int nb = 0; nb < 8; ++nb) {
            s[nb][0] = exp2f(s[nb][0] - nm0);
            s[nb][1] = exp2f(s[nb][1] - nm0);
            s[nb][2] = exp2f(s[nb][2] - nm1);
            s[nb][3] = exp2f(s[nb][3] - nm1);
            rs0 += s[nb][0] + s[nb][1];
            rs1 += s[nb][2] + s[nb][3];
        }
        rs0 += __shfl_xor_sync(0xffffffffu, rs0, 1);
        rs0 += __shfl_xor_sync(0xffffffffu, rs0, 2);
        rs1 += __shfl_xor_sync(0xffffffffu, rs1, 1);
        rs1 += __shfl_xor_sync(0xffffffffu, rs1, 2);
        l0 = l0 * sc0 + rs0;
        l1 = l1 * sc1 + rs1;

        #pragma unroll
        for (int nb = 0; nb < 8; ++nb) {
            o[nb][0] *= sc0; o[nb][1] *= sc0;
            o[nb][2] *= sc1; o[nb][3] *= sc1;
        }

        #pragma unroll
        for (int t = 0; t < 4; ++t) {
            uint32_t ph[4], pl[4];
            splitpack2(s[2*t  ][0], s[2*t  ][1], ph[0], pl[0]);
            splitpack2(s[2*t  ][2], s[2*t  ][3], ph[1], pl[1]);
            splitpack2(s[2*t+1][0], s[2*t+1][1], ph[2], pl[2]);
            splitpack2(s[2*t+1][2], s[2*t+1][3], ph[3], pl[3]);
            const int voff = (t * 16 + (lane & 15)) * AROW;
            #pragma unroll
            for (int nb = 0; nb < 8; ++nb) {
                uint32_t bh[2], bl[2];
                ldm_x2t(bh, Vh + voff + nb * 8);
                ldm_x2t(bl, Vl + voff + nb * 8);
                mma_bf16(o[nb], ph, bh);
                mma_bf16(o[nb], ph, bl);
                mma_bf16(o[nb], pl, bh);
            }
        }
    }

    float inv0 = 1.f / l0, inv1 = 1.f / l1;
    const size_t row0 = (size_t)b * T_SEQ + qrow0;
    const size_t row1 = (size_t)b * T_SEQ + qrow1;
    #pragma unroll
    for (int nb = 0; nb < 8; ++nb) {
        int cc = h * HD + nb * 8 + cbase;
        uint32_t h01, l01, h23, l23;
        splitpack2(o[nb][0] * inv0, o[nb][1] * inv0, h01, l01);
        splitpack2(o[nb][2] * inv1, o[nb][3] * inv1, h23, l23);
        *(uint32_t*)(yh + row0 * CDIM + cc) = h01;
        *(uint32_t*)(yl + row0 * CDIM + cc) = l01;
        *(uint32_t*)(yh + row1 * CDIM + cc) = h23;
        *(uint32_t*)(yl + row1 * CDIM + cc) = l23;
    }
}

// ---------------------------------------------------------------------------
// kernel_launch
// ---------------------------------------------------------------------------
extern "C" void kernel_launch(void* const* d_in, const int* in_sizes, int n_in,
                              void* d_out, int out_size)
{
    (void)in_sizes; (void)n_in; (void)out_size;
    const float* x      = (const float*)d_in[0];
    const float* W_attn = (const float*)d_in[1];
    const float* b_attn = (const float*)d_in[2];
    const float* W_proj = (const float*)d_in[3];
    const float* b_proj = (const float*)d_in[4];
    float* out = (float*)d_out;

    __nv_bfloat16 *xh, *xl, *qkvh, *qkvl, *yh, *yl, *wah, *wal, *wph, *wpl;
    cudaGetSymbolAddress((void**)&xh,   g_xh);
    cudaGetSymbolAddress((void**)&xl,   g_xl);
    cudaGetSymbolAddress((void**)&qkvh, g_qkvh);
    cudaGetSymbolAddress((void**)&qkvl, g_qkvl);
    cudaGetSymbolAddress((void**)&yh,   g_yh);
    cudaGetSymbolAddress((void**)&yl,   g_yl);
    cudaGetSymbolAddress((void**)&wah,  g_wah);
    cudaGetSymbolAddress((void**)&wal,  g_wal);
    cudaGetSymbolAddress((void**)&wph,  g_wph);
    cudaGetSymbolAddress((void**)&wpl,  g_wpl);

    cudaFuncSetAttribute(gemm_split_bf16, cudaFuncAttributeMaxDynamicSharedMemorySize,
                         GEMM_SMEM_BYTES);
    cudaFuncSetAttribute(flash_attn_tc, cudaFuncAttributeMaxDynamicSharedMemorySize,
                         FLASH_SMEM_BYTES);

    // 1) split x
    {
        int n4 = MROWS * CDIM / 4;
        split_kernel<<<(n4 + 255) / 256, 256>>>(x, xh, xl, n4);
    }
    // 2) split + transpose weights
    {
        dim3 blk(32, 8);
        split_transpose_kernel<<<dim3(3 * CDIM / 32, CDIM / 32), blk>>>(W_attn, wah, wal, CDIM, 3 * CDIM);
        split_transpose_kernel<<<dim3(CDIM / 32, CDIM / 32), blk>>>(W_proj, wph, wpl, CDIM, CDIM);
    }
    // 3) qkv(hi/lo) = split(x @ W_attn + b_attn)   [8192, 3072]
    {
        dim3 grid(3 * CDIM / GBN, MROWS / GBM);   // (24, 64)
        gemm_split_bf16<<<grid, 256, GEMM_SMEM_BYTES>>>(xh, xl, wah, wal, b_attn,
                                                        nullptr, qkvh, qkvl,
                                                        MROWS, 3 * CDIM, CDIM);
    }
    // 4) tensor-core flash attention -> yh/yl  (BQ=128)
    {
        dim3 grid(T_SEQ / 128, NHEAD, BATCH);
        flash_attn_tc<<<grid, 256, FLASH_SMEM_BYTES>>>(qkvh, qkvl, yh, yl);
    }
    // 5) out = y @ W_proj + b_proj   [8192, 1024] fp32
    {
        dim3 grid(CDIM / GBN, MROWS / GBM);       // (8, 64)
        gemm_split_bf16<<<grid, 256, GEMM_SMEM_BYTES>>>(yh, yl, wph, wpl, b_proj,
                                                        out, nullptr, nullptr,
                                                        MROWS, CDIM, CDIM);
    }
}

// round 9
// speedup vs baseline: 3.5371x; 1.1425x over previous
#include <cuda_runtime.h>
#include <cuda_bf16.h>
#include <math.h>
#include <stdint.h>

// Problem constants
#define BATCH   4
#define T_SEQ   2048
#define CDIM    1024
#define NHEAD   16
#define HD      64
#define MROWS   (BATCH * T_SEQ)  // 8192

// ---------------------------------------------------------------------------
// Scratch (allocation-free rule: __device__ globals)
// ---------------------------------------------------------------------------
__device__ __nv_bfloat16 g_xh[(size_t)MROWS * CDIM];
__device__ __nv_bfloat16 g_xl[(size_t)MROWS * CDIM];
__device__ __nv_bfloat16 g_qkvh[(size_t)MROWS * 3 * CDIM];
__device__ __nv_bfloat16 g_qkvl[(size_t)MROWS * 3 * CDIM];
__device__ __nv_bfloat16 g_yh[(size_t)MROWS * CDIM];
__device__ __nv_bfloat16 g_yl[(size_t)MROWS * CDIM];
__device__ __nv_bfloat16 g_wah[(size_t)3 * CDIM * CDIM];   // W_attn^T hi [3072][1024]
__device__ __nv_bfloat16 g_wal[(size_t)3 * CDIM * CDIM];
__device__ __nv_bfloat16 g_wph[(size_t)CDIM * CDIM];
__device__ __nv_bfloat16 g_wpl[(size_t)CDIM * CDIM];

// ---------------------------------------------------------------------------
// PTX helpers (sm_103-safe set only: cp.async / ldmatrix / mma.sync)
// ---------------------------------------------------------------------------
__device__ __forceinline__ void cp16(void* dst, const void* src) {
    uint32_t d = (uint32_t)__cvta_generic_to_shared(dst);
    asm volatile("cp.async.cg.shared.global [%0], [%1], 16;\n" :: "r"(d), "l"(src));
}
__device__ __forceinline__ void cp_commit() {
    asm volatile("cp.async.commit_group;\n" ::: "memory");
}
template <int N> __device__ __forceinline__ void cp_wait() {
    asm volatile("cp.async.wait_group %0;\n" :: "n"(N) : "memory");
}
__device__ __forceinline__ void ldm_x4(uint32_t* r, const void* p) {
    uint32_t a = (uint32_t)__cvta_generic_to_shared(p);
    asm volatile("ldmatrix.sync.aligned.m8n8.x4.shared.b16 {%0,%1,%2,%3},[%4];\n"
                 : "=r"(r[0]), "=r"(r[1]), "=r"(r[2]), "=r"(r[3]) : "r"(a));
}
__device__ __forceinline__ void ldm_x2(uint32_t* r, const void* p) {
    uint32_t a = (uint32_t)__cvta_generic_to_shared(p);
    asm volatile("ldmatrix.sync.aligned.m8n8.x2.shared.b16 {%0,%1},[%2];\n"
                 : "=r"(r[0]), "=r"(r[1]) : "r"(a));
}
__device__ __forceinline__ void ldm_x2t(uint32_t* r, const void* p) {
    uint32_t a = (uint32_t)__cvta_generic_to_shared(p);
    asm volatile("ldmatrix.sync.aligned.m8n8.x2.trans.shared.b16 {%0,%1},[%2];\n"
                 : "=r"(r[0]), "=r"(r[1]) : "r"(a));
}
__device__ __forceinline__ void mma_bf16(float* c, const uint32_t* a, const uint32_t* b) {
    asm volatile(
        "mma.sync.aligned.m16n8k16.row.col.f32.bf16.bf16.f32 "
        "{%0,%1,%2,%3},{%4,%5,%6,%7},{%8,%9},{%0,%1,%2,%3};\n"
        : "+f"(c[0]), "+f"(c[1]), "+f"(c[2]), "+f"(c[3])
        : "r"(a[0]), "r"(a[1]), "r"(a[2]), "r"(a[3]), "r"(b[0]), "r"(b[1]));
}
__device__ __forceinline__ void splitpack2(float a, float b, uint32_t& hi, uint32_t& lo) {
    __nv_bfloat16 ha = __float2bfloat16_rn(a);
    __nv_bfloat16 hb = __float2bfloat16_rn(b);
    __nv_bfloat16 la = __float2bfloat16_rn(a - __bfloat162float(ha));
    __nv_bfloat16 lb = __float2bfloat16_rn(b - __bfloat162float(hb));
    hi = (uint32_t)(*(uint16_t*)&ha) | ((uint32_t)(*(uint16_t*)&hb) << 16);
    lo = (uint32_t)(*(uint16_t*)&la) | ((uint32_t)(*(uint16_t*)&lb) << 16);
}

// ---------------------------------------------------------------------------
// Split conversion: fp32 -> hi + lo bf16
// ---------------------------------------------------------------------------
__global__ __launch_bounds__(256)
void split_kernel(const float* __restrict__ in, __nv_bfloat16* __restrict__ hi,
                  __nv_bfloat16* __restrict__ lo, int n4)
{
    int i = blockIdx.x * blockDim.x + threadIdx.x;
    if (i >= n4) return;
    float4 v = ((const float4*)in)[i];
    __nv_bfloat16 h[4], l[4];
    float vv[4] = {v.x, v.y, v.z, v.w};
    #pragma unroll
    for (int j = 0; j < 4; ++j) {
        h[j] = __float2bfloat16_rn(vv[j]);
        l[j] = __float2bfloat16_rn(vv[j] - __bfloat162float(h[j]));
    }
    ((uint2*)hi)[i] = *(uint2*)h;
    ((uint2*)lo)[i] = *(uint2*)l;
}

// ---------------------------------------------------------------------------
// Split + transpose: W [K][N] fp32 -> hiT, loT [N][K] bf16
// ---------------------------------------------------------------------------
__global__ __launch_bounds__(256)
void split_transpose_kernel(const float* __restrict__ W,
                            __nv_bfloat16* __restrict__ hiT,
                            __nv_bfloat16* __restrict__ loT, int K, int N)
{
    __shared__ float t[32][33];
    int n0 = blockIdx.x * 32;
    int k0 = blockIdx.y * 32;
    int tx = threadIdx.x, ty = threadIdx.y;   // 32 x 8
    #pragma unroll
    for (int r = 0; r < 32; r += 8)
        t[ty + r][tx] = W[(size_t)(k0 + ty + r) * N + n0 + tx];
    __syncthreads();
    #pragma unroll
    for (int r = 0; r < 32; r += 8) {
        float v = t[tx][ty + r];
        __nv_bfloat16 h = __float2bfloat16_rn(v);
        __nv_bfloat16 l = __float2bfloat16_rn(v - __bfloat162float(h));
        size_t o = (size_t)(n0 + ty + r) * K + k0 + tx;
        hiT[o] = h;
        loT[o] = l;
    }
}

// ---------------------------------------------------------------------------
// Split-bf16 mma.sync GEMM (3-term hh+hl+lh), 2-stage cp.async pipeline with
// prefetch issue INTERLEAVED into the MMA stream (4 slices per chunk) so the
// tensor pipe is not idle during copy-issue bursts.
// Tile 128x128x32, 256 threads (8 warps, 2m x 4n), warp tile 64x32, 2 CTAs/SM.
// ---------------------------------------------------------------------------
#define GBM 128
#define GBN 128
#define GBK 32
#define GROW (GBK + 8)                 // padded row: 40 bf16 = 80B
#define A_TILE (GBM * GROW)
#define B_TILE (GBN * GROW)
#define STAGE_ELEMS (2 * A_TILE + 2 * B_TILE)   // 20480 bf16
#define GEMM_SMEM_BYTES (2 * STAGE_ELEMS * 2)   // 81920 B

__global__ __launch_bounds__(256, 2)
void gemm_split_bf16(const __nv_bfloat16* __restrict__ Ah_g,
                     const __nv_bfloat16* __restrict__ Al_g,
                     const __nv_bfloat16* __restrict__ Bh_g,
                     const __nv_bfloat16* __restrict__ Bl_g,
                     const float* __restrict__ bias,
                     float* __restrict__ Cf,
                     __nv_bfloat16* __restrict__ Chi,
                     __nv_bfloat16* __restrict__ Clo,
                     int M, int N, int K)
{
    extern __shared__ __nv_bfloat16 smem[];
    const int tid  = threadIdx.x;
    const int bm   = blockIdx.y * GBM;
    const int bn   = blockIdx.x * GBN;
    const int warp = tid >> 5, lane = tid & 31;
    const int wm   = (warp & 1) * 64;
    const int wn   = (warp >> 1) * 32;

    float acc[4][4][4];
    #pragma unroll
    for (int i = 0; i < 4; ++i)
        #pragma unroll
        for (int j = 0; j < 4; ++j)
            #pragma unroll
            for (int r = 0; r < 4; ++r) acc[i][j][r] = 0.f;

    // One slice of a stage load: p in 0..3. p<2 -> A rows, p>=2 -> B rows.
    // Each thread issues exactly 2 cp16 per slice (8 total per stage).
    auto load_part = [&](int s, int k0, int p) {
        __nv_bfloat16* st = smem + s * STAGE_ELEMS;
        if (p < 2) {
            int c = tid + p * 256;              // 0..511 over GBM*4
            int row = c >> 2, col = (c & 3) * 8;
            size_t g = (size_t)(bm + row) * K + k0 + col;
            cp16(st + row * GROW + col, Ah_g + g);
            cp16(st + A_TILE + row * GROW + col, Al_g + g);
        } else {
            int c = tid + (p - 2) * 256;
            int row = c >> 2, col = (c & 3) * 8;
            size_t g = (size_t)(bn + row) * K + k0 + col;
            cp16(st + 2 * A_TILE + row * GROW + col, Bh_g + g);
            cp16(st + 2 * A_TILE + B_TILE + row * GROW + col, Bl_g + g);
        }
    };

    const int niter = K / GBK;
    #pragma unroll
    for (int p = 0; p < 4; ++p) load_part(0, 0, p);
    cp_commit();

    for (int it = 0; it < niter; ++it) {
        cp_wait<0>();
        __syncthreads();

        const __nv_bfloat16* Ah = smem + (it & 1) * STAGE_ELEMS;
        const __nv_bfloat16* Al = Ah + A_TILE;
        const __nv_bfloat16* Bh = Al + A_TILE;
        const __nv_bfloat16* Bl = Bh + B_TILE;

        const bool pf   = (it + 1 < niter);
        const int  nk0  = (it + 1) * GBK;
        const int  snxt = (it + 1) & 1;

        const int arow = wm + (lane & 15);
        const int brow = wn + (lane & 7);

        #pragma unroll
        for (int kk = 0; kk < GBK; kk += 16) {
            const int acol = kk + (lane >> 4) * 8;
            const int bcol = kk + ((lane >> 3) & 1) * 8;
            const int half = kk >> 4;   // 0 or 1

            uint32_t bfh[4][2], bfl[4][2];
            #pragma unroll
            for (int nt = 0; nt < 4; ++nt) {
                ldm_x2(bfh[nt], Bh + (brow + nt * 8) * GROW + bcol);
                ldm_x2(bfl[nt], Bl + (brow + nt * 8) * GROW + bcol);
            }
            {   // hi-A terms: hh + hl
                uint32_t afh[4][4];
                #pragma unroll
                for (int mt = 0; mt < 4; ++mt)
                    ldm_x4(afh[mt], Ah + (arow + mt * 16) * GROW + acol);
                #pragma unroll
                for (int mt = 0; mt < 4; ++mt)
                    #pragma unroll
                    for (int nt = 0; nt < 4; ++nt)
                        mma_bf16(acc[mt][nt], afh[mt], bfh[nt]);
                if (pf) load_part(snxt, nk0, half * 2);       // slice 0 / 2
                #pragma unroll
                for (int mt = 0; mt < 4; ++mt)
                    #pragma unroll
                    for (int nt = 0; nt < 4; ++nt)
                        mma_bf16(acc[mt][nt], afh[mt], bfl[nt]);
            }
            {   // lo-A term: lh
                uint32_t afl[4][4];
                #pragma unroll
                for (int mt = 0; mt < 4; ++mt)
                    ldm_x4(afl[mt], Al + (arow + mt * 16) * GROW + acol);
                if (pf) load_part(snxt, nk0, half * 2 + 1);   // slice 1 / 3
                #pragma unroll
                for (int mt = 0; mt < 4; ++mt)
                    #pragma unroll
                    for (int nt = 0; nt < 4; ++nt)
                        mma_bf16(acc[mt][nt], afl[mt], bfh[nt]);
            }
        }
        if (pf) cp_commit();
    }

    // Epilogue: bias + store
    #pragma unroll
    for (int mt = 0; mt < 4; ++mt) {
        int r0 = bm + wm + mt * 16 + (lane >> 2);
        #pragma unroll
        for (int nt = 0; nt < 4; ++nt) {
            int cc = bn + wn + nt * 8 + (lane & 3) * 2;
            float b0 = bias[cc], b1 = bias[cc + 1];
            float v0 = acc[mt][nt][0] + b0, v1 = acc[mt][nt][1] + b1;
            float v2 = acc[mt][nt][2] + b0, v3 = acc[mt][nt][3] + b1;
            if (Cf) {
                *(float2*)(Cf + (size_t)r0 * N + cc)       = make_float2(v0, v1);
                *(float2*)(Cf + (size_t)(r0 + 8) * N + cc) = make_float2(v2, v3);
            } else {
                uint32_t h01, l01, h23, l23;
                splitpack2(v0, v1, h01, l01);
                splitpack2(v2, v3, h23, l23);
                *(uint32_t*)(Chi + (size_t)r0 * N + cc)       = h01;
                *(uint32_t*)(Clo + (size_t)r0 * N + cc)       = l01;
                *(uint32_t*)(Chi + (size_t)(r0 + 8) * N + cc) = h23;
                *(uint32_t*)(Clo + (size_t)(r0 + 8) * N + cc) = l23;
            }
        }
    }
}

// ---------------------------------------------------------------------------
// Tensor-core causal flash attention, split-bf16, BQ=128 (8 warps, 256 thr),
// now 2 CTAs/SM so MMA of one CTA hides softmax/sync bubbles of the other.
// ---------------------------------------------------------------------------
#define AROW  72
#define QTILE (128 * AROW)
#define KTILE (64 * AROW)
#define ASTG  (4 * KTILE)
#define FLASH_SMEM_BYTES ((2 * QTILE + 2 * ASTG) * 2)   // 110592 B

__global__ __launch_bounds__(256, 2)
void flash_attn_tc(const __nv_bfloat16* __restrict__ qkvh,
                   const __nv_bfloat16* __restrict__ qkvl,
                   __nv_bfloat16* __restrict__ yh,
                   __nv_bfloat16* __restrict__ yl)
{
    extern __shared__ __nv_bfloat16 sm[];
    __nv_bfloat16* Qh = sm;
    __nv_bfloat16* Ql = sm + QTILE;
    __nv_bfloat16* KV = sm + 2 * QTILE;

    const int qb = gridDim.x - 1 - blockIdx.x;
    const int h  = blockIdx.y;
    const int b  = blockIdx.z;
    const int q0 = qb * 128;
    const int tid = threadIdx.x, warp = tid >> 5, lane = tid & 31;

    const size_t rstride = (size_t)3 * CDIM;
    const size_t base = (size_t)b * T_SEQ * rstride + (size_t)h * HD;

    for (int i = tid; i < 1024; i += 256) {
        int r = i >> 3, ch = i & 7;
        size_t g = base + (size_t)(q0 + r) * rstride + ch * 8;
        cp16(Qh + r * AROW + ch * 8, qkvh + g);
        cp16(Ql + r * AROW + ch * 8, qkvl + g);
    }
    cp_commit();

    auto load_kv = [&](int s, int k0) {
        __nv_bfloat16* Kh = KV + s * ASTG;
        __nv_bfloat16* Kl = Kh + KTILE;
        __nv_bfloat16* Vh = Kl + KTILE;
        __nv_bfloat16* Vl = Vh + KTILE;
        for (int i = tid; i < 512; i += 256) {
            int r = i >> 3, ch = i & 7;
            size_t gk = base + CDIM + (size_t)(k0 + r) * rstride + ch * 8;
            size_t gv = gk + CDIM;
            cp16(Kh + r * AROW + ch * 8, qkvh + gk);
            cp16(Kl + r * AROW + ch * 8, qkvl + gk);
            cp16(Vh + r * AROW + ch * 8, qkvh + gv);
            cp16(Vl + r * AROW + ch * 8, qkvl + gv);
        }
    };
    load_kv(0, 0);
    cp_commit();

    float o[8][4];
    #pragma unroll
    for (int nb = 0; nb < 8; ++nb)
        #pragma unroll
        for (int r = 0; r < 4; ++r) o[nb][r] = 0.f;
    float m0 = -1e30f, m1 = -1e30f, l0 = 0.f, l1 = 0.f;

    const float SC = 0.125f * 1.4426950408889634f;
    const int rin   = lane >> 2;
    const int qrow0 = q0 + warp * 16 + rin;
    const int qrow1 = qrow0 + 8;
    const int cbase = 2 * (lane & 3);

    const int nkt = 2 * qb + 2;
    for (int kt = 0; kt < nkt; ++kt) {
        cp_wait<0>();
        __syncthreads();
        if (kt + 1 < nkt) { load_kv((kt + 1) & 1, (kt + 1) * 64); cp_commit(); }

        const __nv_bfloat16* Kh = KV + (kt & 1) * ASTG;
        const __nv_bfloat16* Kl = Kh + KTILE;
        const __nv_bfloat16* Vh = Kl + KTILE;
        const __nv_bfloat16* Vl = Vh + KTILE;

        float s[8][4];
        #pragma unroll
        for (int nb = 0; nb < 8; ++nb)
            #pragma unroll
            for (int r = 0; r < 4; ++r) s[nb][r] = 0.f;

        #pragma unroll
        for (int ks = 0; ks < 4; ++ks) {
            const int aoff = (warp * 16 + (lane & 15)) * AROW + ks * 16 + (lane >> 4) * 8;
            uint32_t ah[4], al[4];
            ldm_x4(ah, Qh + aoff);
            ldm_x4(al, Ql + aoff);
            #pragma unroll
            for (int nb = 0; nb < 8; ++nb) {
                const int boff = (nb * 8 + (lane & 7)) * AROW + ks * 16 + ((lane >> 3) & 1) * 8;
                uint32_t bh[2], bl[2];
                ldm_x2(bh, Kh + boff);
                ldm_x2(bl, Kl + boff);
                mma_bf16(s[nb], ah, bh);
                mma_bf16(s[nb], ah, bl);
                mma_bf16(s[nb], al, bh);
            }
        }

        const int k0 = kt * 64;
        if (kt >= 2 * qb) {
            #pragma unroll
            for (int nb = 0; nb < 8; ++nb) {
                int c0 = k0 + nb * 8 + cbase;
                s[nb][0] = (c0     <= qrow0) ? s[nb][0] * SC : -1e30f;
                s[nb][1] = (c0 + 1 <= qrow0) ? s[nb][1] * SC : -1e30f;
                s[nb][2] = (c0     <= qrow1) ? s[nb][2] * SC : -1e30f;
                s[nb][3] = (c0 + 1 <= qrow1) ? s[nb][3] * SC : -1e30f;
            }
        } else {
            #pragma unroll
            for (int nb = 0; nb < 8; ++nb)
                #pragma unroll
                for (int r = 0; r < 4; ++r) s[nb][r] *= SC;
        }

        float mx0 = -1e30f, mx1 = -1e30f;
        #pragma unroll
        for (int nb = 0; nb < 8; ++nb) {
            mx0 = fmaxf(mx0, fmaxf(s[nb][0], s[nb][1]));
            mx1 = fmaxf(mx1, fmaxf(s[nb][2], s[nb][3]));
        }
        mx0 = fmaxf(mx0, __shfl_xor_sync(0xffffffffu, mx0, 1));
        mx0 = fmaxf(mx0, __shfl_xor_sync(0xffffffffu, mx0, 2));
        mx1 = fmaxf(mx1, __shfl_xor_sync(0xffffffffu, mx1, 1));
        mx1 = fmaxf(mx1, __shfl_xor_sync(0xffffffffu, mx1, 2));

        float nm0 = fmaxf(m0, mx0), nm1 = fmaxf(m1, mx1);
        float sc0 = exp2f(m0 - nm0), sc1 = exp2f(m1 - nm1);
        m0 = nm0; m1 = nm1;

        float rs0 = 0.f, rs1 = 0.f;
        #pragma unroll
        for (int nb = 0; nb < 8; ++nb) {
            s[nb][0] = exp2f(s[nb][0] - nm0);
            s[nb][1] = exp2f(s[nb][1] - nm0);
            s[nb][2] = exp2f(s[nb][2] - nm1);
            s[nb][3] = exp2f(s[nb][3] - nm1);
            rs0 += s[nb][0] + s[nb][1];
            rs1 += s[nb][2] + s[nb][3];
        }
        rs0 += __shfl_xor_sync(0xffffffffu, rs0, 1);
        rs0 += __shfl_xor_sync(0xffffffffu, rs0, 2);
        rs1 += __shfl_xor_sync(0xffffffffu, rs1, 1);
        rs1 += __shfl_xor_sync(0xffffffffu, rs1, 2);
        l0 = l0 * sc0 + rs0;
        l1 = l1 * sc1 + rs1;

        #pragma unroll
        for (int nb = 0; nb < 8; ++nb) {
            o[nb][0] *= sc0; o[nb][1] *= sc0;
            o[nb][2] *= sc1; o[nb][3] *= sc1;
        }

        #pragma unroll
        for (int t = 0; t < 4; ++t) {
            uint32_t ph[4], pl[4];
            splitpack2(s[2*t  ][0], s[2*t  ][1], ph[0], pl[0]);
            splitpack2(s[2*t  ][2], s[2*t  ][3], ph[1], pl[1]);
            splitpack2(s[2*t+1][0], s[2*t+1][1], ph[2], pl[2]);
            splitpack2(s[2*t+1][2], s[2*t+1][3], ph[3], pl[3]);
            const int voff = (t * 16 + (lane & 15)) * AROW;
            #pragma unroll
            for (int nb = 0; nb < 8; ++nb) {
                uint32_t bh[2], bl[2];
                ldm_x2t(bh, Vh + voff + nb * 8);
                ldm_x2t(bl, Vl + voff + nb * 8);
                mma_bf16(o[nb], ph, bh);
                mma_bf16(o[nb], ph, bl);
                mma_bf16(o[nb], pl, bh);
            }
        }
    }

    float inv0 = 1.f / l0, inv1 = 1.f / l1;
    const size_t row0 = (size_t)b * T_SEQ + qrow0;
    const size_t row1 = (size_t)b * T_SEQ + qrow1;
    #pragma unroll
    for (int nb = 0; nb < 8; ++nb) {
        int cc = h * HD + nb * 8 + cbase;
        uint32_t h01, l01, h23, l23;
        splitpack2(o[nb][0] * inv0, o[nb][1] * inv0, h01, l01);
        splitpack2(o[nb][2] * inv1, o[nb][3] * inv1, h23, l23);
        *(uint32_t*)(yh + row0 * CDIM + cc) = h01;
        *(uint32_t*)(yl + row0 * CDIM + cc) = l01;
        *(uint32_t*)(yh + row1 * CDIM + cc) = h23;
        *(uint32_t*)(yl + row1 * CDIM + cc) = l23;
    }
}

// ---------------------------------------------------------------------------
// kernel_launch
// ---------------------------------------------------------------------------
extern "C" void kernel_launch(void* const* d_in, const int* in_sizes, int n_in,
                              void* d_out, int out_size)
{
    (void)in_sizes; (void)n_in; (void)out_size;
    const float* x      = (const float*)d_in[0];
    const float* W_attn = (const float*)d_in[1];
    const float* b_attn = (const float*)d_in[2];
    const float* W_proj = (const float*)d_in[3];
    const float* b_proj = (const float*)d_in[4];
    float* out = (float*)d_out;

    __nv_bfloat16 *xh, *xl, *qkvh, *qkvl, *yh, *yl, *wah, *wal, *wph, *wpl;
    cudaGetSymbolAddress((void**)&xh,   g_xh);
    cudaGetSymbolAddress((void**)&xl,   g_xl);
    cudaGetSymbolAddress((void**)&qkvh, g_qkvh);
    cudaGetSymbolAddress((void**)&qkvl, g_qkvl);
    cudaGetSymbolAddress((void**)&yh,   g_yh);
    cudaGetSymbolAddress((void**)&yl,   g_yl);
    cudaGetSymbolAddress((void**)&wah,  g_wah);
    cudaGetSymbolAddress((void**)&wal,  g_wal);
    cudaGetSymbolAddress((void**)&wph,  g_wph);
    cudaGetSymbolAddress((void**)&wpl,  g_wpl);

    cudaFuncSetAttribute(gemm_split_bf16, cudaFuncAttributeMaxDynamicSharedMemorySize,
                         GEMM_SMEM_BYTES);
    cudaFuncSetAttribute(flash_attn_tc, cudaFuncAttributeMaxDynamicSharedMemorySize,
                         FLASH_SMEM_BYTES);

    // 1) split x
    {
        int n4 = MROWS * CDIM / 4;
        split_kernel<<<(n4 + 255) / 256, 256>>>(x, xh, xl, n4);
    }
    // 2) split + transpose weights
    {
        dim3 blk(32, 8);
        split_transpose_kernel<<<dim3(3 * CDIM / 32, CDIM / 32), blk>>>(W_attn, wah, wal, CDIM, 3 * CDIM);
        split_transpose_kernel<<<dim3(CDIM / 32, CDIM / 32), blk>>>(W_proj, wph, wpl, CDIM, CDIM);
    }
    // 3) qkv(hi/lo) = split(x @ W_attn + b_attn)   [8192, 3072]
    {
        dim3 grid(3 * CDIM / GBN, MROWS / GBM);   // (24, 64)
        gemm_split_bf16<<<grid, 256, GEMM_SMEM_BYTES>>>(xh, xl, wah, wal, b_attn,
                                                        nullptr, qkvh, qkvl,
                                                        MROWS, 3 * CDIM, CDIM);
    }
    // 4) tensor-core flash attention -> yh/yl  (BQ=128)
    {
        dim3 grid(T_SEQ / 128, NHEAD, BATCH);
        flash_attn_tc<<<grid, 256, FLASH_SMEM_BYTES>>>(qkvh, qkvl, yh, yl);
    }
    // 5) out = y @ W_proj + b_proj   [8192, 1024] fp32
    {
        dim3 grid(CDIM / GBN, MROWS / GBM);       // (8, 64)
        gemm_split_bf16<<<grid, 256, GEMM_SMEM_BYTES>>>(yh, yl, wph, wpl, b_proj,
                                                        out, nullptr, nullptr,
                                                        MROWS, CDIM, CDIM);
    }
}

// round 11
// speedup vs baseline: 3.5395x; 1.0007x over previous
#include <cuda_runtime.h>
#include <cuda_bf16.h>
#include <math.h>
#include <stdint.h>

// Problem constants
#define BATCH   4
#define T_SEQ   2048
#define CDIM    1024
#define NHEAD   16
#define HD      64
#define MROWS   (BATCH * T_SEQ)  // 8192

// ---------------------------------------------------------------------------
// Scratch (allocation-free rule: __device__ globals)
// ---------------------------------------------------------------------------
__device__ __nv_bfloat16 g_xh[(size_t)MROWS * CDIM];
__device__ __nv_bfloat16 g_xl[(size_t)MROWS * CDIM];
__device__ __nv_bfloat16 g_qkvh[(size_t)MROWS * 3 * CDIM];
__device__ __nv_bfloat16 g_qkvl[(size_t)MROWS * 3 * CDIM];
__device__ __nv_bfloat16 g_yh[(size_t)MROWS * CDIM];
__device__ __nv_bfloat16 g_yl[(size_t)MROWS * CDIM];
__device__ __nv_bfloat16 g_wah[(size_t)3 * CDIM * CDIM];   // W_attn^T hi [3072][1024]
__device__ __nv_bfloat16 g_wal[(size_t)3 * CDIM * CDIM];
__device__ __nv_bfloat16 g_wph[(size_t)CDIM * CDIM];
__device__ __nv_bfloat16 g_wpl[(size_t)CDIM * CDIM];

// ---------------------------------------------------------------------------
// PTX helpers (sm_103-safe set only: cp.async / ldmatrix / mma.sync)
// ---------------------------------------------------------------------------
__device__ __forceinline__ void cp16(void* dst, const void* src) {
    uint32_t d = (uint32_t)__cvta_generic_to_shared(dst);
    asm volatile("cp.async.cg.shared.global [%0], [%1], 16;\n" :: "r"(d), "l"(src));
}
__device__ __forceinline__ void cp_commit() {
    asm volatile("cp.async.commit_group;\n" ::: "memory");
}
template <int N> __device__ __forceinline__ void cp_wait() {
    asm volatile("cp.async.wait_group %0;\n" :: "n"(N) : "memory");
}
__device__ __forceinline__ void ldm_x4(uint32_t* r, const void* p) {
    uint32_t a = (uint32_t)__cvta_generic_to_shared(p);
    asm volatile("ldmatrix.sync.aligned.m8n8.x4.shared.b16 {%0,%1,%2,%3},[%4];\n"
                 : "=r"(r[0]), "=r"(r[1]), "=r"(r[2]), "=r"(r[3]) : "r"(a));
}
__device__ __forceinline__ void ldm_x2(uint32_t* r, const void* p) {
    uint32_t a = (uint32_t)__cvta_generic_to_shared(p);
    asm volatile("ldmatrix.sync.aligned.m8n8.x2.shared.b16 {%0,%1},[%2];\n"
                 : "=r"(r[0]), "=r"(r[1]) : "r"(a));
}
__device__ __forceinline__ void ldm_x2t(uint32_t* r, const void* p) {
    uint32_t a = (uint32_t)__cvta_generic_to_shared(p);
    asm volatile("ldmatrix.sync.aligned.m8n8.x2.trans.shared.b16 {%0,%1},[%2];\n"
                 : "=r"(r[0]), "=r"(r[1]) : "r"(a));
}
__device__ __forceinline__ void mma_bf16(float* c, const uint32_t* a, const uint32_t* b) {
    asm volatile(
        "mma.sync.aligned.m16n8k16.row.col.f32.bf16.bf16.f32 "
        "{%0,%1,%2,%3},{%4,%5,%6,%7},{%8,%9},{%0,%1,%2,%3};\n"
        : "+f"(c[0]), "+f"(c[1]), "+f"(c[2]), "+f"(c[3])
        : "r"(a[0]), "r"(a[1]), "r"(a[2]), "r"(a[3]), "r"(b[0]), "r"(b[1]));
}
__device__ __forceinline__ void splitpack2(float a, float b, uint32_t& hi, uint32_t& lo) {
    __nv_bfloat16 ha = __float2bfloat16_rn(a);
    __nv_bfloat16 hb = __float2bfloat16_rn(b);
    __nv_bfloat16 la = __float2bfloat16_rn(a - __bfloat162float(ha));
    __nv_bfloat16 lb = __float2bfloat16_rn(b - __bfloat162float(hb));
    hi = (uint32_t)(*(uint16_t*)&ha) | ((uint32_t)(*(uint16_t*)&hb) << 16);
    lo = (uint32_t)(*(uint16_t*)&la) | ((uint32_t)(*(uint16_t*)&lb) << 16);
}

// ---------------------------------------------------------------------------
// Split conversion: fp32 -> hi + lo bf16
// ---------------------------------------------------------------------------
__global__ __launch_bounds__(256)
void split_kernel(const float* __restrict__ in, __nv_bfloat16* __restrict__ hi,
                  __nv_bfloat16* __restrict__ lo, int n4)
{
    int i = blockIdx.x * blockDim.x + threadIdx.x;
    if (i >= n4) return;
    float4 v = ((const float4*)in)[i];
    __nv_bfloat16 h[4], l[4];
    float vv[4] = {v.x, v.y, v.z, v.w};
    #pragma unroll
    for (int j = 0; j < 4; ++j) {
        h[j] = __float2bfloat16_rn(vv[j]);
        l[j] = __float2bfloat16_rn(vv[j] - __bfloat162float(h[j]));
    }
    ((uint2*)hi)[i] = *(uint2*)h;
    ((uint2*)lo)[i] = *(uint2*)l;
}

// ---------------------------------------------------------------------------
// Split + transpose: W [K][N] fp32 -> hiT, loT [N][K] bf16
// ---------------------------------------------------------------------------
__global__ __launch_bounds__(256)
void split_transpose_kernel(const float* __restrict__ W,
                            __nv_bfloat16* __restrict__ hiT,
                            __nv_bfloat16* __restrict__ loT, int K, int N)
{
    __shared__ float t[32][33];
    int n0 = blockIdx.x * 32;
    int k0 = blockIdx.y * 32;
    int tx = threadIdx.x, ty = threadIdx.y;   // 32 x 8
    #pragma unroll
    for (int r = 0; r < 32; r += 8)
        t[ty + r][tx] = W[(size_t)(k0 + ty + r) * N + n0 + tx];
    __syncthreads();
    #pragma unroll
    for (int r = 0; r < 32; r += 8) {
        float v = t[tx][ty + r];
        __nv_bfloat16 h = __float2bfloat16_rn(v);
        __nv_bfloat16 l = __float2bfloat16_rn(v - __bfloat162float(h));
        size_t o = (size_t)(n0 + ty + r) * K + k0 + tx;
        hiT[o] = h;
        loT[o] = l;
    }
}

// ---------------------------------------------------------------------------
// Split-bf16 mma.sync GEMM (3-term hh+hl+lh), 3-stage cp.async pipeline,
// SW128-swizzled tiles (hi|lo packed per 128B row, chunk ^= row&7), prefetch
// issue interleaved into the MMA stream.
// Tile 128x128x32, 256 threads (8 warps, 2m x 4n), warp tile 64x32, 2 CTAs/SM.
// Stage layout (bytes): A joint tile [128 rows x 128B] at 0, B at 16384.
//   Row r of A: chunks 0..3 = Ah cols [8c,8c+8), chunks 4..7 = Al.
//   Physical chunk position = logical_chunk ^ (r & 7).
// ---------------------------------------------------------------------------
#define GBM 128
#define GBN 128
#define GBK 32
#define TKB 32768                      // stage bytes (16KB A + 16KB B)
#define NSTAGE 3
#define GEMM_SMEM_BYTES (NSTAGE * TKB) // 98304 B

__global__ __launch_bounds__(256, 2)
void gemm_split_bf16(const __nv_bfloat16* __restrict__ Ah_g,
                     const __nv_bfloat16* __restrict__ Al_g,
                     const __nv_bfloat16* __restrict__ Bh_g,
                     const __nv_bfloat16* __restrict__ Bl_g,
                     const float* __restrict__ bias,
                     float* __restrict__ Cf,
                     __nv_bfloat16* __restrict__ Chi,
                     __nv_bfloat16* __restrict__ Clo,
                     int M, int N, int K)
{
    extern __shared__ char smem[];
    const int tid  = threadIdx.x;
    const int bm   = blockIdx.y * GBM;
    const int bn   = blockIdx.x * GBN;
    const int warp = tid >> 5, lane = tid & 31;
    const int wm   = (warp & 1) * 64;
    const int wn   = (warp >> 1) * 32;

    float acc[4][4][4];
    #pragma unroll
    for (int i = 0; i < 4; ++i)
        #pragma unroll
        for (int j = 0; j < 4; ++j)
            #pragma unroll
            for (int r = 0; r < 4; ++r) acc[i][j][r] = 0.f;

    // One slice of a stage load: p in 0..3. p<2 -> A rows, p>=2 -> B rows.
    // Each thread issues exactly 2 cp16 per slice.
    auto load_part = [&](int s, int k0, int p) {
        char* st = smem + s * TKB;
        if (p < 2) {
            int c = tid + p * 256;              // 0..511
            int row = c >> 2, cc = c & 3;
            size_t g = (size_t)(bm + row) * K + k0 + cc * 8;
            cp16(st + row * 128 + ((cc       ^ (row & 7)) * 16), Ah_g + g);
            cp16(st + row * 128 + (((cc | 4) ^ (row & 7)) * 16), Al_g + g);
        } else {
            int c = tid + (p - 2) * 256;
            int row = c >> 2, cc = c & 3;
            size_t g = (size_t)(bn + row) * K + k0 + cc * 8;
            char* bt = st + 16384;
            cp16(bt + row * 128 + ((cc       ^ (row & 7)) * 16), Bh_g + g);
            cp16(bt + row * 128 + (((cc | 4) ^ (row & 7)) * 16), Bl_g + g);
        }
    };

    const int niter = K / GBK;
    #pragma unroll
    for (int p = 0; p < 4; ++p) load_part(0, 0, p);
    cp_commit();
    #pragma unroll
    for (int p = 0; p < 4; ++p) load_part(1, GBK, p);
    cp_commit();

    int sc = 0, sn = 2;   // compute stage, prefetch-target stage (mod 3)
    for (int it = 0; it < niter; ++it) {
        if (it + 1 < niter) cp_wait<1>(); else cp_wait<0>();
        __syncthreads();

        const char* Ab = smem + sc * TKB;
        const char* Bb = Ab + 16384;

        const bool pf  = (it + 2 < niter);
        const int  nk0 = (it + 2) * GBK;

        const int arow0 = wm + (lane & 15);
        const int brow0 = wn + (lane & 7);

        #pragma unroll
        for (int kk = 0; kk < GBK; kk += 16) {
            const int half = kk >> 4;                     // 0 or 1
            const int ac   = (kk >> 3) + (lane >> 4);     // A hi chunk 0..3
            const int bc   = (kk >> 3) + ((lane >> 3) & 1);

            uint32_t bfh[4][2], bfl[4][2];
            #pragma unroll
            for (int nt = 0; nt < 4; ++nt) {
                int row = brow0 + nt * 8;
                ldm_x2(bfh[nt], Bb + row * 128 + ((bc       ^ (row & 7)) * 16));
                ldm_x2(bfl[nt], Bb + row * 128 + (((bc | 4) ^ (row & 7)) * 16));
            }
            {   // hi-A terms: hh + hl
                uint32_t afh[4][4];
                #pragma unroll
                for (int mt = 0; mt < 4; ++mt) {
                    int row = arow0 + mt * 16;
                    ldm_x4(afh[mt], Ab + row * 128 + ((ac ^ (row & 7)) * 16));
                }
                #pragma unroll
                for (int mt = 0; mt < 4; ++mt)
                    #pragma unroll
                    for (int nt = 0; nt < 4; ++nt)
                        mma_bf16(acc[mt][nt], afh[mt], bfh[nt]);
                if (pf) load_part(sn, nk0, half * 2);       // slice 0 / 2
                #pragma unroll
                for (int mt = 0; mt < 4; ++mt)
                    #pragma unroll
                    for (int nt = 0; nt < 4; ++nt)
                        mma_bf16(acc[mt][nt], afh[mt], bfl[nt]);
            }
            {   // lo-A term: lh
                uint32_t afl[4][4];
                #pragma unroll
                for (int mt = 0; mt < 4; ++mt) {
                    int row = arow0 + mt * 16;
                    ldm_x4(afl[mt], Ab + row * 128 + (((ac | 4) ^ (row & 7)) * 16));
                }
                if (pf) load_part(sn, nk0, half * 2 + 1);   // slice 1 / 3
                #pragma unroll
                for (int mt = 0; mt < 4; ++mt)
                    #pragma unroll
                    for (int nt = 0; nt < 4; ++nt)
                        mma_bf16(acc[mt][nt], afl[mt], bfh[nt]);
            }
        }
        if (pf) cp_commit();
        sc = (sc + 1 == NSTAGE) ? 0 : sc + 1;
        sn = (sn + 1 == NSTAGE) ? 0 : sn + 1;
    }

    // Epilogue: bias + store
    #pragma unroll
    for (int mt = 0; mt < 4; ++mt) {
        int r0 = bm + wm + mt * 16 + (lane >> 2);
        #pragma unroll
        for (int nt = 0; nt < 4; ++nt) {
            int cc = bn + wn + nt * 8 + (lane & 3) * 2;
            float b0 = bias[cc], b1 = bias[cc + 1];
            float v0 = acc[mt][nt][0] + b0, v1 = acc[mt][nt][1] + b1;
            float v2 = acc[mt][nt][2] + b0, v3 = acc[mt][nt][3] + b1;
            if (Cf) {
                *(float2*)(Cf + (size_t)r0 * N + cc)       = make_float2(v0, v1);
                *(float2*)(Cf + (size_t)(r0 + 8) * N + cc) = make_float2(v2, v3);
            } else {
                uint32_t h01, l01, h23, l23;
                splitpack2(v0, v1, h01, l01);
                splitpack2(v2, v3, h23, l23);
                *(uint32_t*)(Chi + (size_t)r0 * N + cc)       = h01;
                *(uint32_t*)(Clo + (size_t)r0 * N + cc)       = l01;
                *(uint32_t*)(Chi + (size_t)(r0 + 8) * N + cc) = h23;
                *(uint32_t*)(Clo + (size_t)(r0 + 8) * N + cc) = l23;
            }
        }
    }
}

// ---------------------------------------------------------------------------
// Tensor-core causal flash attention, split-bf16, BQ=128 (8 warps, 256 thr),
// 2 CTAs/SM. (unchanged from R8 passing version)
// ---------------------------------------------------------------------------
#define AROW  72
#define QTILE (128 * AROW)
#define KTILE (64 * AROW)
#define ASTG  (4 * KTILE)
#define FLASH_SMEM_BYTES ((2 * QTILE + 2 * ASTG) * 2)   // 110592 B

__global__ __launch_bounds__(256, 2)
void flash_attn_tc(const __nv_bfloat16* __restrict__ qkvh,
                   const __nv_bfloat16* __restrict__ qkvl,
                   __nv_bfloat16* __restrict__ yh,
                   __nv_bfloat16* __restrict__ yl)
{
    extern __shared__ __nv_bfloat16 sm[];
    __nv_bfloat16* Qh = sm;
    __nv_bfloat16* Ql = sm + QTILE;
    __nv_bfloat16* KV = sm + 2 * QTILE;

    const int qb = gridDim.x - 1 - blockIdx.x;
    const int h  = blockIdx.y;
    const int b  = blockIdx.z;
    const int q0 = qb * 128;
    const int tid = threadIdx.x, warp = tid >> 5, lane = tid & 31;

    const size_t rstride = (size_t)3 * CDIM;
    const size_t base = (size_t)b * T_SEQ * rstride + (size_t)h * HD;

    for (int i = tid; i < 1024; i += 256) {
        int r = i >> 3, ch = i & 7;
        size_t g = base + (size_t)(q0 + r) * rstride + ch * 8;
        cp16(Qh + r * AROW + ch * 8, qkvh + g);
        cp16(Ql + r * AROW + ch * 8, qkvl + g);
    }
    cp_commit();

    auto load_kv = [&](int s, int k0) {
        __nv_bfloat16* Kh = KV + s * ASTG;
        __nv_bfloat16* Kl = Kh + KTILE;
        __nv_bfloat16* Vh = Kl + KTILE;
        __nv_bfloat16* Vl = Vh + KTILE;
        for (int i = tid; i < 512; i += 256) {
            int r = i >> 3, ch = i & 7;
            size_t gk = base + CDIM + (size_t)(k0 + r) * rstride + ch * 8;
            size_t gv = gk + CDIM;
            cp16(Kh + r * AROW + ch * 8, qkvh + gk);
            cp16(Kl + r * AROW + ch * 8, qkvl + gk);
            cp16(Vh + r * AROW + ch * 8, qkvh + gv);
            cp16(Vl + r * AROW + ch * 8, qkvl + gv);
        }
    };
    load_kv(0, 0);
    cp_commit();

    float o[8][4];
    #pragma unroll
    for (int nb = 0; nb < 8; ++nb)
        #pragma unroll
        for (int r = 0; r < 4; ++r) o[nb][r] = 0.f;
    float m0 = -1e30f, m1 = -1e30f, l0 = 0.f, l1 = 0.f;

    const float SC = 0.125f * 1.4426950408889634f;
    const int rin   = lane >> 2;
    const int qrow0 = q0 + warp * 16 + rin;
    const int qrow1 = qrow0 + 8;
    const int cbase = 2 * (lane & 3);

    const int nkt = 2 * qb + 2;
    for (int kt = 0; kt < nkt; ++kt) {
        cp_wait<0>();
        __syncthreads();
        if (kt + 1 < nkt) { load_kv((kt + 1) & 1, (kt + 1) * 64); cp_commit(); }

        const __nv_bfloat16* Kh = KV + (kt & 1) * ASTG;
        const __nv_bfloat16* Kl = Kh + KTILE;
        const __nv_bfloat16* Vh = Kl + KTILE;
        const __nv_bfloat16* Vl = Vh + KTILE;

        float s[8][4];
        #pragma unroll
        for (int nb = 0; nb < 8; ++nb)
            #pragma unroll
            for (int r = 0; r < 4; ++r) s[nb][r] = 0.f;

        #pragma unroll
        for (int ks = 0; ks < 4; ++ks) {
            const int aoff = (warp * 16 + (lane & 15)) * AROW + ks * 16 + (lane >> 4) * 8;
            uint32_t ah[4], al[4];
            ldm_x4(ah, Qh + aoff);
            ldm_x4(al, Ql + aoff);
            #pragma unroll
            for (int nb = 0; nb < 8; ++nb) {
                const int boff = (nb * 8 + (lane & 7)) * AROW + ks * 16 + ((lane >> 3) & 1) * 8;
                uint32_t bh[2], bl[2];
                ldm_x2(bh, Kh + boff);
                ldm_x2(bl, Kl + boff);
                mma_bf16(s[nb], ah, bh);
                mma_bf16(s[nb], ah, bl);
                mma_bf16(s[nb], al, bh);
            }
        }

        const int k0 = kt * 64;
        if (kt >= 2 * qb) {
            #pragma unroll
            for (int nb = 0; nb < 8; ++nb) {
                int c0 = k0 + nb * 8 + cbase;
                s[nb][0] = (c0     <= qrow0) ? s[nb][0] * SC : -1e30f;
                s[nb][1] = (c0 + 1 <= qrow0) ? s[nb][1] * SC : -1e30f;
                s[nb][2] = (c0     <= qrow1) ? s[nb][2] * SC : -1e30f;
                s[nb][3] = (c0 + 1 <= qrow1) ? s[nb][3] * SC : -1e30f;
            }
        } else {
            #pragma unroll
            for (int nb = 0; nb < 8; ++nb)
                #pragma unroll
                for (int r = 0; r < 4; ++r) s[nb][r] *= SC;
        }

        float mx0 = -1e30f, mx1 = -1e30f;
        #pragma unroll
        for (int nb = 0; nb < 8; ++nb) {
            mx0 = fmaxf(mx0, fmaxf(s[nb][0], s[nb][1]));
            mx1 = fmaxf(mx1, fmaxf(s[nb][2], s[nb][3]));
        }
        mx0 = fmaxf(mx0, __shfl_xor_sync(0xffffffffu, mx0, 1));
        mx0 = fmaxf(mx0, __shfl_xor_sync(0xffffffffu, mx0, 2));
        mx1 = fmaxf(mx1, __shfl_xor_sync(0xffffffffu, mx1, 1));
        mx1 = fmaxf(mx1, __shfl_xor_sync(0xffffffffu, mx1, 2));

        float nm0 = fmaxf(m0, mx0), nm1 = fmaxf(m1, mx1);
        float sc0 = exp2f(m0 - nm0), sc1 = exp2f(m1 - nm1);
        m0 = nm0; m1 = nm1;

        float rs0 = 0.f, rs1 = 0.f;
        #pragma unroll
        for (int nb = 0; nb < 8; ++nb) {
            s[nb][0] = exp2f(s[nb][0] - nm0);
            s[nb][1] = exp2f(s[nb][1] - nm0);
            s[nb][2] = exp2f(s[nb][2] - nm1);
            s[nb][3] = exp2f(s[nb][3] - nm1);
            rs0 += s[nb][0] + s[nb][1];
            rs1 += s[nb][2] + s[nb][3];
        }
        rs0 += __shfl_xor_sync(0xffffffffu, rs0, 1);
        rs0 += __shfl_xor_sync(0xffffffffu, rs0, 2);
        rs1 += __shfl_xor_sync(0xffffffffu, rs1, 1);
        rs1 += __shfl_xor_sync(0xffffffffu, rs1, 2);
        l0 = l0 * sc0 + rs0;
        l1 = l1 * sc1 + rs1;

        #pragma unroll
        for (int nb = 0; nb < 8; ++nb) {
            o[nb][0] *= sc0; o[nb][1] *= sc0;
            o[nb][2] *= sc1; o[nb][3] *= sc1;
        }

        #pragma unroll
        for (int t = 0; t < 4; ++t) {
            uint32_t ph[4], pl[4];
            splitpack2(s[2*t  ][0], s[2*t  ][1], ph[0], pl[0]);
            splitpack2(s[2*t  ][2], s[2*t  ][3], ph[1], pl[1]);
            splitpack2(s[2*t+1][0], s[2*t+1][1], ph[2], pl[2]);
            splitpack2(s[2*t+1][2], s[2*t+1][3], ph[3], pl[3]);
            const int voff = (t * 16 + (lane & 15)) * AROW;
            #pragma unroll
            for (int nb = 0; nb < 8; ++nb) {
                uint32_t bh[2], bl[2];
                ldm_x2t(bh, Vh + voff + nb * 8);
                ldm_x2t(bl, Vl + voff + nb * 8);
                mma_bf16(o[nb], ph, bh);
                mma_bf16(o[nb], ph, bl);
                mma_bf16(o[nb], pl, bh);
            }
        }
    }

    float inv0 = 1.f / l0, inv1 = 1.f / l1;
    const size_t row0 = (size_t)b * T_SEQ + qrow0;
    const size_t row1 = (size_t)b * T_SEQ + qrow1;
    #pragma unroll
    for (int nb = 0; nb < 8; ++nb) {
        int cc = h * HD + nb * 8 + cbase;
        uint32_t h01, l01, h23, l23;
        splitpack2(o[nb][0] * inv0, o[nb][1] * inv0, h01, l01);
        splitpack2(o[nb][2] * inv1, o[nb][3] * inv1, h23, l23);
        *(uint32_t*)(yh + row0 * CDIM + cc) = h01;
        *(uint32_t*)(yl + row0 * CDIM + cc) = l01;
        *(uint32_t*)(yh + row1 * CDIM + cc) = h23;
        *(uint32_t*)(yl + row1 * CDIM + cc) = l23;
    }
}

// ---------------------------------------------------------------------------
// kernel_launch
// ---------------------------------------------------------------------------
extern "C" void kernel_launch(void* const* d_in, const int* in_sizes, int n_in,
                              void* d_out, int out_size)
{
    (void)in_sizes; (void)n_in; (void)out_size;
    const float* x      = (const float*)d_in[0];
    const float* W_attn = (const float*)d_in[1];
    const float* b_attn = (const float*)d_in[2];
    const float* W_proj = (const float*)d_in[3];
    const float* b_proj = (const float*)d_in[4];
    float* out = (float*)d_out;

    __nv_bfloat16 *xh, *xl, *qkvh, *qkvl, *yh, *yl, *wah, *wal, *wph, *wpl;
    cudaGetSymbolAddress((void**)&xh,   g_xh);
    cudaGetSymbolAddress((void**)&xl,   g_xl);
    cudaGetSymbolAddress((void**)&qkvh, g_qkvh);
    cudaGetSymbolAddress((void**)&qkvl, g_qkvl);
    cudaGetSymbolAddress((void**)&yh,   g_yh);
    cudaGetSymbolAddress((void**)&yl,   g_yl);
    cudaGetSymbolAddress((void**)&wah,  g_wah);
    cudaGetSymbolAddress((void**)&wal,  g_wal);
    cudaGetSymbolAddress((void**)&wph,  g_wph);
    cudaGetSymbolAddress((void**)&wpl,  g_wpl);

    cudaFuncSetAttribute(gemm_split_bf16, cudaFuncAttributeMaxDynamicSharedMemorySize,
                         GEMM_SMEM_BYTES);
    cudaFuncSetAttribute(flash_attn_tc, cudaFuncAttributeMaxDynamicSharedMemorySize,
                         FLASH_SMEM_BYTES);

    // 1) split x
    {
        int n4 = MROWS * CDIM / 4;
        split_kernel<<<(n4 + 255) / 256, 256>>>(x, xh, xl, n4);
    }
    // 2) split + transpose weights
    {
        dim3 blk(32, 8);
        split_transpose_kernel<<<dim3(3 * CDIM / 32, CDIM / 32), blk>>>(W_attn, wah, wal, CDIM, 3 * CDIM);
        split_transpose_kernel<<<dim3(CDIM / 32, CDIM / 32), blk>>>(W_proj, wph, wpl, CDIM, CDIM);
    }
    // 3) qkv(hi/lo) = split(x @ W_attn + b_attn)   [8192, 3072]
    {
        dim3 grid(3 * CDIM / GBN, MROWS / GBM);   // (24, 64)
        gemm_split_bf16<<<grid, 256, GEMM_SMEM_BYTES>>>(xh, xl, wah, wal, b_attn,
                                                        nullptr, qkvh, qkvl,
                                                        MROWS, 3 * CDIM, CDIM);
    }
    // 4) tensor-core flash attention -> yh/yl  (BQ=128)
    {
        dim3 grid(T_SEQ / 128, NHEAD, BATCH);
        flash_attn_tc<<<grid, 256, FLASH_SMEM_BYTES>>>(qkvh, qkvl, yh, yl);
    }
    // 5) out = y @ W_proj + b_proj   [8192, 1024] fp32
    {
        dim3 grid(CDIM / GBN, MROWS / GBM);       // (8, 64)
        gemm_split_bf16<<<grid, 256, GEMM_SMEM_BYTES>>>(yh, yl, wph, wpl, b_proj,
                                                        out, nullptr, nullptr,
                                                        MROWS, CDIM, CDIM);
    }
}

// round 12
// speedup vs baseline: 3.5982x; 1.0166x over previous
#include <cuda_runtime.h>
#include <cuda_bf16.h>
#include <math.h>
#include <stdint.h>

// Problem constants
#define BATCH   4
#define T_SEQ   2048
#define CDIM    1024
#define NHEAD   16
#define HD      64
#define MROWS   (BATCH * T_SEQ)  // 8192

// ---------------------------------------------------------------------------
// Scratch (allocation-free rule: __device__ globals)
// ---------------------------------------------------------------------------
__device__ __nv_bfloat16 g_xh[(size_t)MROWS * CDIM];
__device__ __nv_bfloat16 g_xl[(size_t)MROWS * CDIM];
__device__ __nv_bfloat16 g_qkvh[(size_t)MROWS * 3 * CDIM];
__device__ __nv_bfloat16 g_qkvl[(size_t)MROWS * 3 * CDIM];
__device__ __nv_bfloat16 g_yh[(size_t)MROWS * CDIM];
__device__ __nv_bfloat16 g_yl[(size_t)MROWS * CDIM];
__device__ __nv_bfloat16 g_wah[(size_t)3 * CDIM * CDIM];   // W_attn^T hi [3072][1024]
__device__ __nv_bfloat16 g_wal[(size_t)3 * CDIM * CDIM];
__device__ __nv_bfloat16 g_wph[(size_t)CDIM * CDIM];
__device__ __nv_bfloat16 g_wpl[(size_t)CDIM * CDIM];

// ---------------------------------------------------------------------------
// PTX helpers (sm_103-safe set only: cp.async / ldmatrix / mma.sync)
// ---------------------------------------------------------------------------
__device__ __forceinline__ void cp16(void* dst, const void* src) {
    uint32_t d = (uint32_t)__cvta_generic_to_shared(dst);
    asm volatile("cp.async.cg.shared.global [%0], [%1], 16;\n" :: "r"(d), "l"(src));
}
__device__ __forceinline__ void cp16r(uint32_t d, const void* src) {
    asm volatile("cp.async.cg.shared.global [%0], [%1], 16;\n" :: "r"(d), "l"(src));
}
__device__ __forceinline__ void cp_commit() {
    asm volatile("cp.async.commit_group;\n" ::: "memory");
}
template <int N> __device__ __forceinline__ void cp_wait() {
    asm volatile("cp.async.wait_group %0;\n" :: "n"(N) : "memory");
}
__device__ __forceinline__ void ldm_x4(uint32_t* r, const void* p) {
    uint32_t a = (uint32_t)__cvta_generic_to_shared(p);
    asm volatile("ldmatrix.sync.aligned.m8n8.x4.shared.b16 {%0,%1,%2,%3},[%4];\n"
                 : "=r"(r[0]), "=r"(r[1]), "=r"(r[2]), "=r"(r[3]) : "r"(a));
}
__device__ __forceinline__ void ldm_x2(uint32_t* r, const void* p) {
    uint32_t a = (uint32_t)__cvta_generic_to_shared(p);
    asm volatile("ldmatrix.sync.aligned.m8n8.x2.shared.b16 {%0,%1},[%2];\n"
                 : "=r"(r[0]), "=r"(r[1]) : "r"(a));
}
__device__ __forceinline__ void ldm_x2t(uint32_t* r, const void* p) {
    uint32_t a = (uint32_t)__cvta_generic_to_shared(p);
    asm volatile("ldmatrix.sync.aligned.m8n8.x2.trans.shared.b16 {%0,%1},[%2];\n"
                 : "=r"(r[0]), "=r"(r[1]) : "r"(a));
}
// raw-address variants (caller supplies shared-window u32 address)
__device__ __forceinline__ void ldm_x4r(uint32_t* r, uint32_t a) {
    asm volatile("ldmatrix.sync.aligned.m8n8.x4.shared.b16 {%0,%1,%2,%3},[%4];\n"
                 : "=r"(r[0]), "=r"(r[1]), "=r"(r[2]), "=r"(r[3]) : "r"(a));
}
__device__ __forceinline__ void ldm_x2r(uint32_t* r, uint32_t a) {
    asm volatile("ldmatrix.sync.aligned.m8n8.x2.shared.b16 {%0,%1},[%2];\n"
                 : "=r"(r[0]), "=r"(r[1]) : "r"(a));
}
__device__ __forceinline__ void mma_bf16(float* c, const uint32_t* a, const uint32_t* b) {
    asm volatile(
        "mma.sync.aligned.m16n8k16.row.col.f32.bf16.bf16.f32 "
        "{%0,%1,%2,%3},{%4,%5,%6,%7},{%8,%9},{%0,%1,%2,%3};\n"
        : "+f"(c[0]), "+f"(c[1]), "+f"(c[2]), "+f"(c[3])
        : "r"(a[0]), "r"(a[1]), "r"(a[2]), "r"(a[3]), "r"(b[0]), "r"(b[1]));
}
__device__ __forceinline__ void splitpack2(float a, float b, uint32_t& hi, uint32_t& lo) {
    __nv_bfloat16 ha = __float2bfloat16_rn(a);
    __nv_bfloat16 hb = __float2bfloat16_rn(b);
    __nv_bfloat16 la = __float2bfloat16_rn(a - __bfloat162float(ha));
    __nv_bfloat16 lb = __float2bfloat16_rn(b - __bfloat162float(hb));
    hi = (uint32_t)(*(uint16_t*)&ha) | ((uint32_t)(*(uint16_t*)&hb) << 16);
    lo = (uint32_t)(*(uint16_t*)&la) | ((uint32_t)(*(uint16_t*)&lb) << 16);
}

// ---------------------------------------------------------------------------
// Split conversion: fp32 -> hi + lo bf16
// ---------------------------------------------------------------------------
__global__ __launch_bounds__(256)
void split_kernel(const float* __restrict__ in, __nv_bfloat16* __restrict__ hi,
                  __nv_bfloat16* __restrict__ lo, int n4)
{
    int i = blockIdx.x * blockDim.x + threadIdx.x;
    if (i >= n4) return;
    float4 v = ((const float4*)in)[i];
    __nv_bfloat16 h[4], l[4];
    float vv[4] = {v.x, v.y, v.z, v.w};
    #pragma unroll
    for (int j = 0; j < 4; ++j) {
        h[j] = __float2bfloat16_rn(vv[j]);
        l[j] = __float2bfloat16_rn(vv[j] - __bfloat162float(h[j]));
    }
    ((uint2*)hi)[i] = *(uint2*)h;
    ((uint2*)lo)[i] = *(uint2*)l;
}

// ---------------------------------------------------------------------------
// Split + transpose: W [K][N] fp32 -> hiT, loT [N][K] bf16
// ---------------------------------------------------------------------------
__global__ __launch_bounds__(256)
void split_transpose_kernel(const float* __restrict__ W,
                            __nv_bfloat16* __restrict__ hiT,
                            __nv_bfloat16* __restrict__ loT, int K, int N)
{
    __shared__ float t[32][33];
    int n0 = blockIdx.x * 32;
    int k0 = blockIdx.y * 32;
    int tx = threadIdx.x, ty = threadIdx.y;   // 32 x 8
    #pragma unroll
    for (int r = 0; r < 32; r += 8)
        t[ty + r][tx] = W[(size_t)(k0 + ty + r) * N + n0 + tx];
    __syncthreads();
    #pragma unroll
    for (int r = 0; r < 32; r += 8) {
        float v = t[tx][ty + r];
        __nv_bfloat16 h = __float2bfloat16_rn(v);
        __nv_bfloat16 l = __float2bfloat16_rn(v - __bfloat162float(h));
        size_t o = (size_t)(n0 + ty + r) * K + k0 + tx;
        hiT[o] = h;
        loT[o] = l;
    }
}

// ---------------------------------------------------------------------------
// Split-bf16 mma.sync GEMM (3-term hh+hl+lh), 3-stage cp.async pipeline,
// SW128-swizzled tiles, interleaved prefetch. Addresses hoisted per chunk
// (kk=16 -> ^32, lo-half -> ^64) and A fragments consumed per-mt to keep
// live registers under the 128/thread cap (no spills).
// Tile 128x128x32, 256 threads (8 warps, 2m x 4n), warp tile 64x32, 2 CTAs/SM.
// ---------------------------------------------------------------------------
#define GBM 128
#define GBN 128
#define GBK 32
#define TKB 32768                      // stage bytes (16KB A + 16KB B)
#define NSTAGE 3
#define GEMM_SMEM_BYTES (NSTAGE * TKB) // 98304 B

__global__ __launch_bounds__(256, 2)
void gemm_split_bf16(const __nv_bfloat16* __restrict__ Ah_g,
                     const __nv_bfloat16* __restrict__ Al_g,
                     const __nv_bfloat16* __restrict__ Bh_g,
                     const __nv_bfloat16* __restrict__ Bl_g,
                     const float* __restrict__ bias,
                     float* __restrict__ Cf,
                     __nv_bfloat16* __restrict__ Chi,
                     __nv_bfloat16* __restrict__ Clo,
                     int M, int N, int K)
{
    extern __shared__ char smem[];
    const uint32_t smem32 = (uint32_t)__cvta_generic_to_shared(smem);
    const int tid  = threadIdx.x;
    const int bm   = blockIdx.y * GBM;
    const int bn   = blockIdx.x * GBN;
    const int warp = tid >> 5, lane = tid & 31;
    const int wm   = (warp & 1) * 64;
    const int wn   = (warp >> 1) * 32;

    float acc[4][4][4];
    #pragma unroll
    for (int i = 0; i < 4; ++i)
        #pragma unroll
        for (int j = 0; j < 4; ++j)
            #pragma unroll
            for (int r = 0; r < 4; ++r) acc[i][j][r] = 0.f;

    // One slice of a stage load: p in 0..3. p<2 -> A rows, p>=2 -> B rows.
    auto load_part = [&](int s, int k0, int p) {
        uint32_t st = smem32 + s * TKB;
        if (p < 2) {
            int c = tid + p * 256;              // 0..511
            int row = c >> 2, cc = c & 3;
            size_t g = (size_t)(bm + row) * K + k0 + cc * 8;
            uint32_t d = st + row * 128 + ((cc ^ (row & 7)) * 16);
            cp16r(d,      Ah_g + g);
            cp16r(d ^ 64, Al_g + g);
        } else {
            int c = tid + (p - 2) * 256;
            int row = c >> 2, cc = c & 3;
            size_t g = (size_t)(bn + row) * K + k0 + cc * 8;
            uint32_t d = st + 16384 + row * 128 + ((cc ^ (row & 7)) * 16);
            cp16r(d,      Bh_g + g);
            cp16r(d ^ 64, Bl_g + g);
        }
    };

    const int niter = K / GBK;
    #pragma unroll
    for (int p = 0; p < 4; ++p) load_part(0, 0, p);
    cp_commit();
    #pragma unroll
    for (int p = 0; p < 4; ++p) load_part(1, GBK, p);
    cp_commit();

    const int arow0 = wm + (lane & 15);
    const int brow0 = wn + (lane & 7);
    const int ac0   = lane >> 4;          // 0/1
    const int bc0   = (lane >> 3) & 1;    // 0/1

    int sc = 0, sn = 2;   // compute stage, prefetch-target stage (mod 3)
    for (int it = 0; it < niter; ++it) {
        if (it + 1 < niter) cp_wait<1>(); else cp_wait<0>();
        __syncthreads();

        // Hoisted swizzled base addresses for this chunk (kk=0, hi half).
        uint32_t aab = smem32 + sc * TKB;
        uint32_t aA[4], bA[4];
        #pragma unroll
        for (int mt = 0; mt < 4; ++mt) {
            int row = arow0 + mt * 16;
            aA[mt] = aab + row * 128 + ((ac0 ^ (row & 7)) * 16);
        }
        #pragma unroll
        for (int nt = 0; nt < 4; ++nt) {
            int row = brow0 + nt * 8;
            bA[nt] = aab + 16384 + row * 128 + ((bc0 ^ (row & 7)) * 16);
        }

        const bool pf  = (it + 2 < niter);
        const int  nk0 = (it + 2) * GBK;

        #pragma unroll
        for (int half = 0; half < 2; ++half) {
            const uint32_t ko = half * 32;   // kk=16 -> chunk+2 -> ^32

            uint32_t bfh[4][2], bfl[4][2];
            #pragma unroll
            for (int nt = 0; nt < 4; ++nt) {
                ldm_x2r(bfh[nt], bA[nt] ^ ko);
                ldm_x2r(bfl[nt], bA[nt] ^ ko ^ 64);
            }
            // hi-A terms: hh + hl, A fragment consumed per-mt (4 live regs)
            #pragma unroll
            for (int mt = 0; mt < 4; ++mt) {
                uint32_t afh[4];
                ldm_x4r(afh, aA[mt] ^ ko);
                #pragma unroll
                for (int nt = 0; nt < 4; ++nt)
                    mma_bf16(acc[mt][nt], afh, bfh[nt]);
                if (pf && mt == 1) load_part(sn, nk0, half * 2);
                #pragma unroll
                for (int nt = 0; nt < 4; ++nt)
                    mma_bf16(acc[mt][nt], afh, bfl[nt]);
            }
            // lo-A term: lh
            #pragma unroll
            for (int mt = 0; mt < 4; ++mt) {
                uint32_t afl[4];
                ldm_x4r(afl, aA[mt] ^ ko ^ 64);
                if (pf && mt == 1) load_part(sn, nk0, half * 2 + 1);
                #pragma unroll
                for (int nt = 0; nt < 4; ++nt)
                    mma_bf16(acc[mt][nt], afl, bfh[nt]);
            }
        }
        if (pf) cp_commit();
        sc = (sc + 1 == NSTAGE) ? 0 : sc + 1;
        sn = (sn + 1 == NSTAGE) ? 0 : sn + 1;
    }

    // Epilogue: bias + store
    #pragma unroll
    for (int mt = 0; mt < 4; ++mt) {
        int r0 = bm + wm + mt * 16 + (lane >> 2);
        #pragma unroll
        for (int nt = 0; nt < 4; ++nt) {
            int cc = bn + wn + nt * 8 + (lane & 3) * 2;
            float b0 = bias[cc], b1 = bias[cc + 1];
            float v0 = acc[mt][nt][0] + b0, v1 = acc[mt][nt][1] + b1;
            float v2 = acc[mt][nt][2] + b0, v3 = acc[mt][nt][3] + b1;
            if (Cf) {
                *(float2*)(Cf + (size_t)r0 * N + cc)       = make_float2(v0, v1);
                *(float2*)(Cf + (size_t)(r0 + 8) * N + cc) = make_float2(v2, v3);
            } else {
                uint32_t h01, l01, h23, l23;
                splitpack2(v0, v1, h01, l01);
                splitpack2(v2, v3, h23, l23);
                *(uint32_t*)(Chi + (size_t)r0 * N + cc)       = h01;
                *(uint32_t*)(Clo + (size_t)r0 * N + cc)       = l01;
                *(uint32_t*)(Chi + (size_t)(r0 + 8) * N + cc) = h23;
                *(uint32_t*)(Clo + (size_t)(r0 + 8) * N + cc) = l23;
            }
        }
    }
}

// ---------------------------------------------------------------------------
// Tensor-core causal flash attention, split-bf16, BQ=128 (8 warps, 256 thr),
// 2 CTAs/SM. Row-sum shuffle reduction deferred until after PV MMAs.
// ---------------------------------------------------------------------------
#define AROW  72
#define QTILE (128 * AROW)
#define KTILE (64 * AROW)
#define ASTG  (4 * KTILE)
#define FLASH_SMEM_BYTES ((2 * QTILE + 2 * ASTG) * 2)   // 110592 B

__global__ __launch_bounds__(256, 2)
void flash_attn_tc(const __nv_bfloat16* __restrict__ qkvh,
                   const __nv_bfloat16* __restrict__ qkvl,
                   __nv_bfloat16* __restrict__ yh,
                   __nv_bfloat16* __restrict__ yl)
{
    extern __shared__ __nv_bfloat16 sm[];
    __nv_bfloat16* Qh = sm;
    __nv_bfloat16* Ql = sm + QTILE;
    __nv_bfloat16* KV = sm + 2 * QTILE;

    const int qb = gridDim.x - 1 - blockIdx.x;
    const int h  = blockIdx.y;
    const int b  = blockIdx.z;
    const int q0 = qb * 128;
    const int tid = threadIdx.x, warp = tid >> 5, lane = tid & 31;

    const size_t rstride = (size_t)3 * CDIM;
    const size_t base = (size_t)b * T_SEQ * rstride + (size_t)h * HD;

    for (int i = tid; i < 1024; i += 256) {
        int r = i >> 3, ch = i & 7;
        size_t g = base + (size_t)(q0 + r) * rstride + ch * 8;
        cp16(Qh + r * AROW + ch * 8, qkvh + g);
        cp16(Ql + r * AROW + ch * 8, qkvl + g);
    }
    cp_commit();

    auto load_kv = [&](int s, int k0) {
        __nv_bfloat16* Kh = KV + s * ASTG;
        __nv_bfloat16* Kl = Kh + KTILE;
        __nv_bfloat16* Vh = Kl + KTILE;
        __nv_bfloat16* Vl = Vh + KTILE;
        for (int i = tid; i < 512; i += 256) {
            int r = i >> 3, ch = i & 7;
            size_t gk = base + CDIM + (size_t)(k0 + r) * rstride + ch * 8;
            size_t gv = gk + CDIM;
            cp16(Kh + r * AROW + ch * 8, qkvh + gk);
            cp16(Kl + r * AROW + ch * 8, qkvl + gk);
            cp16(Vh + r * AROW + ch * 8, qkvh + gv);
            cp16(Vl + r * AROW + ch * 8, qkvl + gv);
        }
    };
    load_kv(0, 0);
    cp_commit();

    float o[8][4];
    #pragma unroll
    for (int nb = 0; nb < 8; ++nb)
        #pragma unroll
        for (int r = 0; r < 4; ++r) o[nb][r] = 0.f;
    float m0 = -1e30f, m1 = -1e30f, l0 = 0.f, l1 = 0.f;

    const float SC = 0.125f * 1.4426950408889634f;
    const int rin   = lane >> 2;
    const int qrow0 = q0 + warp * 16 + rin;
    const int qrow1 = qrow0 + 8;
    const int cbase = 2 * (lane & 3);

    const int nkt = 2 * qb + 2;
    for (int kt = 0; kt < nkt; ++kt) {
        cp_wait<0>();
        __syncthreads();
        if (kt + 1 < nkt) { load_kv((kt + 1) & 1, (kt + 1) * 64); cp_commit(); }

        const __nv_bfloat16* Kh = KV + (kt & 1) * ASTG;
        const __nv_bfloat16* Kl = Kh + KTILE;
        const __nv_bfloat16* Vh = Kl + KTILE;
        const __nv_bfloat16* Vl = Vh + KTILE;

        float s[8][4];
        #pragma unroll
        for (int nb = 0; nb < 8; ++nb)
            #pragma unroll
            for (int r = 0; r < 4; ++r) s[nb][r] = 0.f;

        #pragma unroll
        for (int ks = 0; ks < 4; ++ks) {
            const int aoff = (warp * 16 + (lane & 15)) * AROW + ks * 16 + (lane >> 4) * 8;
            uint32_t ah[4], al[4];
            ldm_x4(ah, Qh + aoff);
            ldm_x4(al, Ql + aoff);
            #pragma unroll
            for (int nb = 0; nb < 8; ++nb) {
                const int boff = (nb * 8 + (lane & 7)) * AROW + ks * 16 + ((lane >> 3) & 1) * 8;
                uint32_t bh[2], bl[2];
                ldm_x2(bh, Kh + boff);
                ldm_x2(bl, Kl + boff);
                mma_bf16(s[nb], ah, bh);
                mma_bf16(s[nb], ah, bl);
                mma_bf16(s[nb], al, bh);
            }
        }

        const int k0 = kt * 64;
        if (kt >= 2 * qb) {
            #pragma unroll
            for (int nb = 0; nb < 8; ++nb) {
                int c0 = k0 + nb * 8 + cbase;
                s[nb][0] = (c0     <= qrow0) ? s[nb][0] * SC : -1e30f;
                s[nb][1] = (c0 + 1 <= qrow0) ? s[nb][1] * SC : -1e30f;
                s[nb][2] = (c0     <= qrow1) ? s[nb][2] * SC : -1e30f;
                s[nb][3] = (c0 + 1 <= qrow1) ? s[nb][3] * SC : -1e30f;
            }
        } else {
            #pragma unroll
            for (int nb = 0; nb < 8; ++nb)
                #pragma unroll
                for (int r = 0; r < 4; ++r) s[nb][r] *= SC;
        }

        float mx0 = -1e30f, mx1 = -1e30f;
        #pragma unroll
        for (int nb = 0; nb < 8; ++nb) {
            mx0 = fmaxf(mx0, fmaxf(s[nb][0], s[nb][1]));
            mx1 = fmaxf(mx1, fmaxf(s[nb][2], s[nb][3]));
        }
        mx0 = fmaxf(mx0, __shfl_xor_sync(0xffffffffu, mx0, 1));
        mx0 = fmaxf(mx0, __shfl_xor_sync(0xffffffffu, mx0, 2));
        mx1 = fmaxf(mx1, __shfl_xor_sync(0xffffffffu, mx1, 1));
        mx1 = fmaxf(mx1, __shfl_xor_sync(0xffffffffu, mx1, 2));

        float nm0 = fmaxf(m0, mx0), nm1 = fmaxf(m1, mx1);
        float sc0 = exp2f(m0 - nm0), sc1 = exp2f(m1 - nm1);
        m0 = nm0; m1 = nm1;

        // exp + per-thread partial sums (cross-lane reduction deferred)
        float rs0 = 0.f, rs1 = 0.f;
        #pragma unroll
        for (int nb = 0; nb < 8; ++nb) {
            s[nb][0] = exp2f(s[nb][0] - nm0);
            s[nb][1] = exp2f(s[nb][1] - nm0);
            s[nb][2] = exp2f(s[nb][2] - nm1);
            s[nb][3] = exp2f(s[nb][3] - nm1);
            rs0 += s[nb][0] + s[nb][1];
            rs1 += s[nb][2] + s[nb][3];
        }

        #pragma unroll
        for (int nb = 0; nb < 8; ++nb) {
            o[nb][0] *= sc0; o[nb][1] *= sc0;
            o[nb][2] *= sc1; o[nb][3] *= sc1;
        }

        #pragma unroll
        for (int t = 0; t < 4; ++t) {
            uint32_t ph[4], pl[4];
            splitpack2(s[2*t  ][0], s[2*t  ][1], ph[0], pl[0]);
            splitpack2(s[2*t  ][2], s[2*t  ][3], ph[1], pl[1]);
            splitpack2(s[2*t+1][0], s[2*t+1][1], ph[2], pl[2]);
            splitpack2(s[2*t+1][2], s[2*t+1][3], ph[3], pl[3]);
            const int voff = (t * 16 + (lane & 15)) * AROW;
            #pragma unroll
            for (int nb = 0; nb < 8; ++nb) {
                uint32_t bh[2], bl[2];
                ldm_x2t(bh, Vh + voff + nb * 8);
                ldm_x2t(bl, Vl + voff + nb * 8);
                mma_bf16(o[nb], ph, bh);
                mma_bf16(o[nb], ph, bl);
                mma_bf16(o[nb], pl, bh);
            }
        }

        // deferred row-sum reduction (l not needed until epilogue)
        rs0 += __shfl_xor_sync(0xffffffffu, rs0, 1);
        rs0 += __shfl_xor_sync(0xffffffffu, rs0, 2);
        rs1 += __shfl_xor_sync(0xffffffffu, rs1, 1);
        rs1 += __shfl_xor_sync(0xffffffffu, rs1, 2);
        l0 = l0 * sc0 + rs0;
        l1 = l1 * sc1 + rs1;
    }

    float inv0 = 1.f / l0, inv1 = 1.f / l1;
    const size_t row0 = (size_t)b * T_SEQ + qrow0;
    const size_t row1 = (size_t)b * T_SEQ + qrow1;
    #pragma unroll
    for (int nb = 0; nb < 8; ++nb) {
        int cc = h * HD + nb * 8 + cbase;
        uint32_t h01, l01, h23, l23;
        splitpack2(o[nb][0] * inv0, o[nb][1] * inv0, h01, l01);
        splitpack2(o[nb][2] * inv1, o[nb][3] * inv1, h23, l23);
        *(uint32_t*)(yh + row0 * CDIM + cc) = h01;
        *(uint32_t*)(yl + row0 * CDIM + cc) = l01;
        *(uint32_t*)(yh + row1 * CDIM + cc) = h23;
        *(uint32_t*)(yl + row1 * CDIM + cc) = l23;
    }
}

// ---------------------------------------------------------------------------
// kernel_launch
// ---------------------------------------------------------------------------
extern "C" void kernel_launch(void* const* d_in, const int* in_sizes, int n_in,
                              void* d_out, int out_size)
{
    (void)in_sizes; (void)n_in; (void)out_size;
    const float* x      = (const float*)d_in[0];
    const float* W_attn = (const float*)d_in[1];
    const float* b_attn = (const float*)d_in[2];
    const float* W_proj = (const float*)d_in[3];
    const float* b_proj = (const float*)d_in[4];
    float* out = (float*)d_out;

    __nv_bfloat16 *xh, *xl, *qkvh, *qkvl, *yh, *yl, *wah, *wal, *wph, *wpl;
    cudaGetSymbolAddress((void**)&xh,   g_xh);
    cudaGetSymbolAddress((void**)&xl,   g_xl);
    cudaGetSymbolAddress((void**)&qkvh, g_qkvh);
    cudaGetSymbolAddress((void**)&qkvl, g_qkvl);
    cudaGetSymbolAddress((void**)&yh,   g_yh);
    cudaGetSymbolAddress((void**)&yl,   g_yl);
    cudaGetSymbolAddress((void**)&wah,  g_wah);
    cudaGetSymbolAddress((void**)&wal,  g_wal);
    cudaGetSymbolAddress((void**)&wph,  g_wph);
    cudaGetSymbolAddress((void**)&wpl,  g_wpl);

    cudaFuncSetAttribute(gemm_split_bf16, cudaFuncAttributeMaxDynamicSharedMemorySize,
                         GEMM_SMEM_BYTES);
    cudaFuncSetAttribute(flash_attn_tc, cudaFuncAttributeMaxDynamicSharedMemorySize,
                         FLASH_SMEM_BYTES);

    // 1) split x
    {
        int n4 = MROWS * CDIM / 4;
        split_kernel<<<(n4 + 255) / 256, 256>>>(x, xh, xl, n4);
    }
    // 2) split + transpose weights
    {
        dim3 blk(32, 8);
        split_transpose_kernel<<<dim3(3 * CDIM / 32, CDIM / 32), blk>>>(W_attn, wah, wal, CDIM, 3 * CDIM);
        split_transpose_kernel<<<dim3(CDIM / 32, CDIM / 32), blk>>>(W_proj, wph, wpl, CDIM, CDIM);
    }
    // 3) qkv(hi/lo) = split(x @ W_attn + b_attn)   [8192, 3072]
    {
        dim3 grid(3 * CDIM / GBN, MROWS / GBM);   // (24, 64)
        gemm_split_bf16<<<grid, 256, GEMM_SMEM_BYTES>>>(xh, xl, wah, wal, b_attn,
                                                        nullptr, qkvh, qkvl,
                                                        MROWS, 3 * CDIM, CDIM);
    }
    // 4) tensor-core flash attention -> yh/yl  (BQ=128)
    {
        dim3 grid(T_SEQ / 128, NHEAD, BATCH);
        flash_attn_tc<<<grid, 256, FLASH_SMEM_BYTES>>>(qkvh, qkvl, yh, yl);
    }
    // 5) out = y @ W_proj + b_proj   [8192, 1024] fp32
    {
        dim3 grid(CDIM / GBN, MROWS / GBM);       // (8, 64)
        gemm_split_bf16<<<grid, 256, GEMM_SMEM_BYTES>>>(yh, yl, wph, wpl, b_proj,
                                                        out, nullptr, nullptr,
                                                        MROWS, CDIM, CDIM);
    }
}